// round 1
// baseline (speedup 1.0000x reference)
#include <cuda_runtime.h>
#include <math.h>

// Problem constants
#define BATCH 8
#define CIN   128
#define HW    3136        // 56*56
#define NPIX  25088       // 8*3136
#define MID   64
#define OUTC  256
#define KTOT  4096        // 64*64
#define EPS   1e-5f

// Scratch (device globals: allocation-free rule)
__device__ float g_p1[(size_t)MID * NPIX];      // [m][pix]   6.4 MB
__device__ float g_p2[(size_t)MID * NPIX];      // [d][pix]   6.4 MB
__device__ float g_WpT[(size_t)KTOT * OUTC];    // [k][o]     4.0 MB

// ---------------------------------------------------------------------------
// Wp transpose: WpT[k][o] = Wp[o][k]   (k = c*64 + d)
// ---------------------------------------------------------------------------
__global__ void transpose_wp_kernel(const float* __restrict__ Wp) {
    int idx = blockIdx.x * 256 + threadIdx.x;   // 0 .. 1048575
    int k = idx >> 8;
    int o = idx & 255;
    g_WpT[idx] = Wp[(size_t)o * KTOT + k];
}

// ---------------------------------------------------------------------------
// Projection: p[m][pix] = sum_c W[m][c] * x[b][c][hw]
// Block = 64-pixel tile (within one b), 256 threads, 4m x 4pix per thread.
// ---------------------------------------------------------------------------
__global__ __launch_bounds__(256)
void proj_kernel(const float* __restrict__ x, const float* __restrict__ Wm, int which) {
    __shared__ float Ws[CIN][MID];   // [c][m] 32 KB
    float* p = which ? g_p2 : g_p1;

    int t = threadIdx.x;
    // transposed load of W (64x128): reads strided (L1 absorbs), STS conflict-free
    for (int idx = t; idx < MID * CIN; idx += 256) {
        int c = idx >> 6;
        int m = idx & 63;
        Ws[c][m] = __ldg(&Wm[m * CIN + c]);
    }
    __syncthreads();

    int pixg0 = blockIdx.x * 64;
    int b   = pixg0 / HW;
    int hw0 = pixg0 - b * HW;

    int tx = t & 15;   // pixel group: pixels tx*4 .. +3
    int ty = t >> 4;   // m group:     m = ty*4 .. +3

    const float* xb = x + (size_t)b * CIN * HW + hw0 + tx * 4;

    float acc[4][4];
#pragma unroll
    for (int mi = 0; mi < 4; mi++)
#pragma unroll
        for (int pi = 0; pi < 4; pi++) acc[mi][pi] = 0.0f;

#pragma unroll 4
    for (int c = 0; c < CIN; c++) {
        float4 xv = *(const float4*)(xb + (size_t)c * HW);
        float4 wv = *(const float4*)&Ws[c][ty * 4];
        float xs[4] = {xv.x, xv.y, xv.z, xv.w};
        float wsv[4] = {wv.x, wv.y, wv.z, wv.w};
#pragma unroll
        for (int mi = 0; mi < 4; mi++)
#pragma unroll
            for (int pi = 0; pi < 4; pi++)
                acc[mi][pi] += wsv[mi] * xs[pi];
    }

#pragma unroll
    for (int mi = 0; mi < 4; mi++) {
        float4 v = make_float4(acc[mi][0], acc[mi][1], acc[mi][2], acc[mi][3]);
        *(float4*)(p + (size_t)(ty * 4 + mi) * NPIX + pixg0 + tx * 4) = v;
    }
}

// ---------------------------------------------------------------------------
// Main bilinear contraction + LayerNorm + exact GELU.
// Block = 64 pixels x 256 o. 256 threads, 8pix x 8o register tile.
// Thread map: pg = t&7 owns pixels {pg + 8*i}, og = t>>3 owns o {og*8 + j}.
// ---------------------------------------------------------------------------
__global__ __launch_bounds__(256)
void bilinear_kernel(const float* __restrict__ gamma,
                     const float* __restrict__ beta,
                     float* __restrict__ out) {
    __shared__ float p1s[MID][64];   // [c][pix] 16 KB
    __shared__ float p2s[MID][64];   // [d][pix] 16 KB
    __shared__ float ws[16][OUTC];   //          16 KB   -> 48 KB total

    int t = threadIdx.x;
    int pixg0 = blockIdx.x * 64;
    int b   = pixg0 / HW;
    int hw0 = pixg0 - b * HW;

    // Load p1/p2 tiles (coalesced: [m][pix] layout, pix contiguous)
    for (int r = t; r < MID * 16; r += 256) {
        int c = r >> 4;
        int q = r & 15;
        ((float4*)p1s[c])[q] = *(const float4*)(g_p1 + (size_t)c * NPIX + pixg0 + q * 4);
        ((float4*)p2s[c])[q] = *(const float4*)(g_p2 + (size_t)c * NPIX + pixg0 + q * 4);
    }

    int pg = t & 7;
    int og = t >> 3;

    float acc[8][8];
#pragma unroll
    for (int i = 0; i < 8; i++)
#pragma unroll
        for (int j = 0; j < 8; j++) acc[i][j] = 0.0f;

    for (int k0 = 0; k0 < KTOT; k0 += 16) {
        __syncthreads();   // ws consumers done (also covers p-tile visibility on iter 0)
        // Load ws[kk][o] from WpT (fully coalesced)
        for (int r = t; r < 16 * 64; r += 256) {
            int kk = r >> 6;
            int q  = r & 63;
            ((float4*)ws[kk])[q] = *(const float4*)(g_WpT + (size_t)(k0 + kk) * OUTC + q * 4);
        }
        __syncthreads();

        int c  = k0 >> 6;     // constant within chunk (16 | 64)
        int d0 = k0 & 63;

        float p1v[8];
#pragma unroll
        for (int i = 0; i < 8; i++) p1v[i] = p1s[c][pg + 8 * i];

#pragma unroll
        for (int kk = 0; kk < 16; kk++) {
            int d = d0 + kk;
            float av[8];
#pragma unroll
            for (int i = 0; i < 8; i++) av[i] = p1v[i] * p2s[d][pg + 8 * i];

            float4 w0 = ((const float4*)ws[kk])[og * 2];
            float4 w1 = ((const float4*)ws[kk])[og * 2 + 1];
            float wv[8] = {w0.x, w0.y, w0.z, w0.w, w1.x, w1.y, w1.z, w1.w};
#pragma unroll
            for (int i = 0; i < 8; i++)
#pragma unroll
                for (int j = 0; j < 8; j++)
                    acc[i][j] += av[i] * wv[j];
        }
    }

    // -------- LayerNorm over the 256 o-channels per pixel --------
    float s[8], ss[8];
#pragma unroll
    for (int i = 0; i < 8; i++) {
        float a = 0.0f, a2 = 0.0f;
#pragma unroll
        for (int j = 0; j < 8; j++) {
            float v = acc[i][j];
            a += v;
            a2 += v * v;
        }
        s[i] = a; ss[i] = a2;
    }
    // Reduce within warp over the 4 lanes sharing a pixel group (stride 8)
#pragma unroll
    for (int ofs = 8; ofs <= 16; ofs <<= 1) {
#pragma unroll
        for (int i = 0; i < 8; i++) {
            s[i]  += __shfl_xor_sync(0xffffffffu, s[i],  ofs);
            ss[i] += __shfl_xor_sync(0xffffffffu, ss[i], ofs);
        }
    }
    // Cross-warp partials: reuse p1s as scratch
    float* red = &p1s[0][0];   // [warp][pg][i][2] = 8*8*8*2 floats
    int warp = t >> 5;
    int lane = t & 31;
    __syncthreads();           // all p1s readers done
    if (lane < 8) {
#pragma unroll
        for (int i = 0; i < 8; i++) {
            red[((warp * 8 + pg) * 8 + i) * 2 + 0] = s[i];
            red[((warp * 8 + pg) * 8 + i) * 2 + 1] = ss[i];
        }
    }
    __syncthreads();

    float mu[8], rs[8];
#pragma unroll
    for (int i = 0; i < 8; i++) {
        float S = 0.0f, SS = 0.0f;
#pragma unroll
        for (int w = 0; w < 8; w++) {
            S  += red[((w * 8 + pg) * 8 + i) * 2 + 0];
            SS += red[((w * 8 + pg) * 8 + i) * 2 + 1];
        }
        float m = S * (1.0f / OUTC);
        float var = SS * (1.0f / OUTC) - m * m;
        mu[i] = m;
        rs[i] = rsqrtf(var + EPS);
    }

    // -------- gamma/beta + exact-erf GELU + store (NCHW) --------
#pragma unroll
    for (int j = 0; j < 8; j++) {
        int o = og * 8 + j;
        float g  = __ldg(&gamma[o]);
        float be = __ldg(&beta[o]);
        float* ob = out + ((size_t)(b * OUTC + o)) * HW + hw0 + pg;
#pragma unroll
        for (int i = 0; i < 8; i++) {
            float x = (acc[i][j] - mu[i]) * rs[i] * g + be;
            float y = 0.5f * x * (1.0f + erff(x * 0.70710678118654752f));
            ob[8 * i] = y;
        }
    }
}

// ---------------------------------------------------------------------------
extern "C" void kernel_launch(void* const* d_in, const int* in_sizes, int n_in,
                              void* d_out, int out_size) {
    const float* x1    = (const float*)d_in[0];
    const float* x2    = (const float*)d_in[1];
    const float* W1    = (const float*)d_in[2];
    const float* W2    = (const float*)d_in[3];
    const float* Wp    = (const float*)d_in[4];
    const float* gamma = (const float*)d_in[5];
    const float* beta  = (const float*)d_in[6];
    float* out = (float*)d_out;

    transpose_wp_kernel<<<(KTOT * OUTC) / 256, 256>>>(Wp);
    proj_kernel<<<NPIX / 64, 256>>>(x1, W1, 0);
    proj_kernel<<<NPIX / 64, 256>>>(x2, W2, 1);
    bilinear_kernel<<<NPIX / 64, 256>>>(gamma, beta, out);
}

// round 3
// speedup vs baseline: 1.6849x; 1.6849x over previous
#include <cuda_runtime.h>
#include <cuda_bf16.h>
#include <cstdint>
#include <math.h>

// Problem constants
#define BATCH 8
#define CIN   128
#define HW    3136        // 56*56
#define NPIX  25088       // 8*3136
#define MID   64
#define OUTC  256
#define KTOT  4096        // 64*64
#define EPS   1e-5f

// Scratch (device globals: allocation-free rule)
__device__ __align__(16) float g_p1[(size_t)MID * NPIX];             // [m][pix]
__device__ __align__(16) float g_p2[(size_t)MID * NPIX];             // [d][pix]
__device__ __align__(16) __nv_bfloat16 g_Wh[(size_t)OUTC * KTOT];    // hi split, native Wp layout
__device__ __align__(16) __nv_bfloat16 g_Wl[(size_t)OUTC * KTOT];    // lo split

// ---------------------------------------------------------------------------
// Helpers (arch-portable PTX only: cp.async / ldmatrix / mma.sync)
// ---------------------------------------------------------------------------
__device__ __forceinline__ uint32_t smem_u32(const void* p) {
    uint32_t a;
    asm("{ .reg .u64 t; cvta.to.shared.u64 t, %1; cvt.u32.u64 %0, t; }" : "=r"(a) : "l"(p));
    return a;
}
__device__ __forceinline__ void cp16(uint32_t dst, const void* src) {
    asm volatile("cp.async.cg.shared.global [%0], [%1], 16;\n" :: "r"(dst), "l"(src));
}
#define CP_COMMIT() asm volatile("cp.async.commit_group;\n" ::: "memory")
#define CP_WAIT(n)  asm volatile("cp.async.wait_group %0;\n" :: "n"(n) : "memory")

__device__ __forceinline__ void ldsm_x4(uint32_t& r0, uint32_t& r1, uint32_t& r2, uint32_t& r3,
                                        uint32_t addr) {
    asm volatile("ldmatrix.sync.aligned.m8n8.x4.shared.b16 {%0,%1,%2,%3}, [%4];"
                 : "=r"(r0), "=r"(r1), "=r"(r2), "=r"(r3) : "r"(addr));
}
__device__ __forceinline__ void mma16816(float* c, const uint32_t* a, const uint32_t* b) {
    asm volatile(
        "mma.sync.aligned.m16n8k16.row.col.f32.bf16.bf16.f32 "
        "{%0,%1,%2,%3}, {%4,%5,%6,%7}, {%8,%9}, {%0,%1,%2,%3};"
        : "+f"(c[0]), "+f"(c[1]), "+f"(c[2]), "+f"(c[3])
        : "r"(a[0]), "r"(a[1]), "r"(a[2]), "r"(a[3]), "r"(b[0]), "r"(b[1]));
}

#define SWZ(off) ((off) ^ (((off) >> 3) & 0x70))

// ---------------------------------------------------------------------------
// SMEM layout (bytes). Tiles are rows of 128B (64 bf16), SW128-swizzled.
// ---------------------------------------------------------------------------
#define OFF_P1   0          // p1 tile [c][pix] 64x128 fp32 = 32768
#define OFF_AH   32768      // A hi 128x64 bf16 = 16384
#define OFF_AL   49152      // A lo
#define OFF_BH0  65536      // B hi stage0 256x64 bf16 = 32768
#define OFF_BH1  98304
#define OFF_BL0  131072
#define OFF_BL1  163840
#define OFF_GB   196608     // gamma 256 + beta 256 fp32 = 2048
#define SMEM_TOTAL 198656
// Epilogue D tile reuses [0, 132096): 128 rows x 258 fp32 (padded stride)
#define DSTRIDE  258

// ---------------------------------------------------------------------------
// Wp bf16 hi/lo split (native [o][k] layout preserved)
// ---------------------------------------------------------------------------
__global__ void wsplit_kernel(const float* __restrict__ Wp) {
    int idx = blockIdx.x * 256 + threadIdx.x;
    float w = Wp[idx];
    __nv_bfloat16 h = __float2bfloat16(w);
    g_Wh[idx] = h;
    g_Wl[idx] = __float2bfloat16(w - __bfloat162float(h));
}

// ---------------------------------------------------------------------------
// Projection: p[m][pix] = sum_c W[m][c] * x[b][c][hw]   (validated in R1)
// ---------------------------------------------------------------------------
__global__ __launch_bounds__(256)
void proj_kernel(const float* __restrict__ x, const float* __restrict__ Wm, int which) {
    __shared__ float Ws[CIN][MID];
    float* p = which ? g_p2 : g_p1;

    int t = threadIdx.x;
    for (int idx = t; idx < MID * CIN; idx += 256) {
        int c = idx >> 6;
        int m = idx & 63;
        Ws[c][m] = __ldg(&Wm[m * CIN + c]);
    }
    __syncthreads();

    int pixg0 = blockIdx.x * 64;
    int b   = pixg0 / HW;
    int hw0 = pixg0 - b * HW;

    int tx = t & 15;
    int ty = t >> 4;

    const float* xb = x + (size_t)b * CIN * HW + hw0 + tx * 4;

    float acc[4][4];
#pragma unroll
    for (int mi = 0; mi < 4; mi++)
#pragma unroll
        for (int pi = 0; pi < 4; pi++) acc[mi][pi] = 0.0f;

#pragma unroll 4
    for (int c = 0; c < CIN; c++) {
        float4 xv = *(const float4*)(xb + (size_t)c * HW);
        float4 wv = *(const float4*)&Ws[c][ty * 4];
        float xs[4] = {xv.x, xv.y, xv.z, xv.w};
        float wsv[4] = {wv.x, wv.y, wv.z, wv.w};
#pragma unroll
        for (int mi = 0; mi < 4; mi++)
#pragma unroll
            for (int pi = 0; pi < 4; pi++)
                acc[mi][pi] += wsv[mi] * xs[pi];
    }

#pragma unroll
    for (int mi = 0; mi < 4; mi++) {
        float4 v = make_float4(acc[mi][0], acc[mi][1], acc[mi][2], acc[mi][3]);
        *(float4*)(p + (size_t)(ty * 4 + mi) * NPIX + pixg0 + tx * 4) = v;
    }
}

// ---------------------------------------------------------------------------
// Main: mma.sync bf16 (hi/lo, 3 passes) GEMM + LN + exact GELU
// CTA: 128 pix x 256 o, K=4096. 512 threads = 16 warps (4 pix-groups x 4 o-groups).
// Warp tile: 32 pix x 64 o -> 64 fp32 accum regs/thread.
// ---------------------------------------------------------------------------
__global__ __launch_bounds__(512, 1)
void bilinear_mma_kernel(const float* __restrict__ gamma,
                         const float* __restrict__ beta,
                         float* __restrict__ out) {
    extern __shared__ char smem[];
    const uint32_t sbase = smem_u32(smem);

    const int t   = threadIdx.x;
    const int wid = t >> 5;
    const int lid = t & 31;
    const int wp  = wid >> 2;   // pixel group: rows wp*32
    const int wo  = wid & 3;    // o group: cols wo*64
    const int pix0 = blockIdx.x * 128;

    // gamma/beta to smem
    {
        float* gb = (float*)(smem + OFF_GB);
        if (t < 256) gb[t] = __ldg(&gamma[t]);
        else gb[256 + (t - 256)] = __ldg(&beta[t - 256]);
    }

    // p1 tile -> smem  [c][128 pix]
    float* p1s = (float*)(smem + OFF_P1);
#pragma unroll
    for (int r = 0; r < 16; r++) {
        int i = t + r * 512;
        int c = i >> 7, px = i & 127;
        p1s[i] = g_p1[(size_t)c * NPIX + pix0 + px];
    }

    // p2 quarter-row in registers: thread owns pixel t>>2, d-range (t&3)*16..+15
    const int apix = t >> 2;
    const int aq   = t & 3;
    float p2r[16];
#pragma unroll
    for (int j = 0; j < 16; j++)
        p2r[j] = g_p2[(size_t)(aq * 16 + j) * NPIX + pix0 + apix];

    const uint32_t offBH[2] = {OFF_BH0, OFF_BH1};
    const uint32_t offBL[2] = {OFF_BL0, OFF_BL1};

    // B prefetch for chunk 0
    {
        const __nv_bfloat16* bh = g_Wh;   // + ch*64, ch=0
        const __nv_bfloat16* bl = g_Wl;
#pragma unroll
        for (int r = 0; r < 4; r++) {
            int idx = t + r * 512;       // 0..2047
            int o   = idx >> 3;
            int seg = idx & 7;
            uint32_t doff = SWZ((uint32_t)(o * 128 + seg * 16));
            cp16(sbase + OFF_BH0 + doff, bh + (size_t)o * KTOT + seg * 8);
            cp16(sbase + OFF_BL0 + doff, bl + (size_t)o * KTOT + seg * 8);
        }
        CP_COMMIT();
    }

    float acc[2][8][4];
#pragma unroll
    for (int mt = 0; mt < 2; mt++)
#pragma unroll
        for (int nt = 0; nt < 8; nt++)
#pragma unroll
            for (int i = 0; i < 4; i++) acc[mt][nt][i] = 0.0f;

    __syncthreads();   // p1s visible

    // Per-lane ldmatrix address components (row part), swizzle applied per use.
    // A (16x16): lanes 0-15 -> rows 0-15 (k-lo), 16-31 -> rows 0-15 (k-hi)
    const int a_row_l = lid & 15;
    const int a_hi16  = (lid >> 4) * 16;
    // B (x4 covers 2 n-tiles): groups of 8 lanes:
    //   g0: o rows 0-7 k-lo | g1: o rows 0-7 k-hi | g2: o rows 8-15 k-lo | g3: k-hi
    const int b_row_l = ((lid >> 4) << 3) + (lid & 7);   // 0-7 then 8-15
    const int b_hi16  = ((lid >> 3) & 1) * 16;

    for (int ch = 0; ch < 64; ch++) {
        const int s = ch & 1;

        // prefetch B for next chunk into alternate stage
        if (ch < 63) {
            const __nv_bfloat16* bh = g_Wh + (size_t)(ch + 1) * 64;
            const __nv_bfloat16* bl = g_Wl + (size_t)(ch + 1) * 64;
#pragma unroll
            for (int r = 0; r < 4; r++) {
                int idx = t + r * 512;
                int o   = idx >> 3;
                int seg = idx & 7;
                uint32_t doff = SWZ((uint32_t)(o * 128 + seg * 16));
                cp16(sbase + offBH[s ^ 1] + doff, bh + (size_t)o * KTOT + seg * 8);
                cp16(sbase + offBL[s ^ 1] + doff, bl + (size_t)o * KTOT + seg * 8);
            }
            CP_COMMIT();
        }

        // build A chunk: a[pix][d] = p1[pix][ch] * p2[pix][d], bf16 hi/lo, SW128
        {
            const float p1v = p1s[ch * 128 + apix];
            char* ah = smem + OFF_AH;
            char* al = smem + OFF_AL;
#pragma unroll
            for (int jj = 0; jj < 8; jj++) {
                float a0 = p1v * p2r[2 * jj];
                float a1 = p1v * p2r[2 * jj + 1];
                uint32_t hp;
                asm("cvt.rn.bf16x2.f32 %0, %1, %2;" : "=r"(hp) : "f"(a1), "f"(a0));
                float h0 = __uint_as_float(hp << 16);
                float h1 = __uint_as_float(hp & 0xFFFF0000u);
                float r0 = a0 - h0;
                float r1 = a1 - h1;
                uint32_t lp;
                asm("cvt.rn.bf16x2.f32 %0, %1, %2;" : "=r"(lp) : "f"(r1), "f"(r0));
                uint32_t boff = SWZ((uint32_t)(apix * 128 + (aq * 16 + 2 * jj) * 2));
                *(uint32_t*)(ah + boff) = hp;
                *(uint32_t*)(al + boff) = lp;
            }
        }

        if (ch < 63) { CP_WAIT(1); } else { CP_WAIT(0); }
        __syncthreads();   // A built + B(ch) landed, visible to all

        // 3 passes: Ah*Bh, Al*Bh, Ah*Bl
        const uint32_t aBase[3] = {sbase + OFF_AH, sbase + OFF_AL, sbase + OFF_AH};
        const uint32_t bBase[3] = {sbase + offBH[s], sbase + offBH[s], sbase + offBL[s]};

#pragma unroll
        for (int pass = 0; pass < 3; pass++) {
            const uint32_t ab = aBase[pass];
            const uint32_t bb = bBase[pass];
#pragma unroll
            for (int kk = 0; kk < 4; kk++) {
                // A fragments: 2 m-tiles of 16 rows
                uint32_t afr[2][4];
#pragma unroll
                for (int mt = 0; mt < 2; mt++) {
                    int row = wp * 32 + mt * 16 + a_row_l;
                    uint32_t addr = ab + SWZ((uint32_t)(row * 128 + kk * 32 + a_hi16));
                    ldsm_x4(afr[mt][0], afr[mt][1], afr[mt][2], afr[mt][3], addr);
                }
                // B fragments: 8 n-tiles via 4 x4-ldmatrix
                uint32_t bfr[8][2];
#pragma unroll
                for (int bp = 0; bp < 4; bp++) {
                    int orow = wo * 64 + bp * 16 + b_row_l;
                    uint32_t addr = bb + SWZ((uint32_t)(orow * 128 + kk * 32 + b_hi16));
                    uint32_t r0, r1, r2, r3;
                    ldsm_x4(r0, r1, r2, r3, addr);
                    bfr[bp * 2][0] = r0;  bfr[bp * 2][1] = r1;
                    bfr[bp * 2 + 1][0] = r2;  bfr[bp * 2 + 1][1] = r3;
                }
#pragma unroll
                for (int mt = 0; mt < 2; mt++)
#pragma unroll
                    for (int nt = 0; nt < 8; nt++)
                        mma16816(acc[mt][nt], afr[mt], bfr[nt]);
            }
        }
        __syncthreads();   // A/B(s) consumed; safe to rebuild/refill
    }

    // --- epilogue: acc -> smem D, per-pixel LN + GELU + store ---
    float* D = (float*)smem;   // reuses p1s/A/B region (all dead)
    // p1s region overlaps D; already synced above.
#pragma unroll
    for (int mt = 0; mt < 2; mt++) {
#pragma unroll
        for (int nt = 0; nt < 8; nt++) {
            int row = wp * 32 + mt * 16 + (lid >> 2);
            int col = wo * 64 + nt * 8 + (lid & 3) * 2;
            *(float2*)&D[row * DSTRIDE + col] = make_float2(acc[mt][nt][0], acc[mt][nt][1]);
            *(float2*)&D[(row + 8) * DSTRIDE + col] = make_float2(acc[mt][nt][2], acc[mt][nt][3]);
        }
    }
    __syncthreads();

    {
        const int pix = t >> 2;
        const int q   = t & 3;
        const float* Drow = D + pix * DSTRIDE + q * 64;
        float s1 = 0.0f, s2 = 0.0f;
#pragma unroll
        for (int j = 0; j < 32; j++) {
            float2 v = *(const float2*)&Drow[j * 2];
            s1 += v.x + v.y;
            s2 += v.x * v.x + v.y * v.y;
        }
        // quad reduce
        s1 += __shfl_xor_sync(0xffffffffu, s1, 1);
        s2 += __shfl_xor_sync(0xffffffffu, s2, 1);
        s1 += __shfl_xor_sync(0xffffffffu, s1, 2);
        s2 += __shfl_xor_sync(0xffffffffu, s2, 2);

        float mu = s1 * (1.0f / OUTC);
        float var = s2 * (1.0f / OUTC) - mu * mu;
        float rs = rsqrtf(var + EPS);

        const int P  = pix0 + pix;
        const int bb = P / HW;
        const int hw = P - bb * HW;
        float* obase = out + (size_t)bb * OUTC * HW + hw;
        const float* sg  = (const float*)(smem + OFF_GB);
        const float* sbt = sg + 256;

#pragma unroll
        for (int j = 0; j < 64; j++) {
            int o = q * 64 + j;
            float x = (Drow[j] - mu) * rs * sg[o] + sbt[o];
            float y = 0.5f * x * (1.0f + erff(x * 0.70710678118654752f));
            obase[(size_t)o * HW] = y;
        }
    }
}

// ---------------------------------------------------------------------------
extern "C" void kernel_launch(void* const* d_in, const int* in_sizes, int n_in,
                              void* d_out, int out_size) {
    const float* x1    = (const float*)d_in[0];
    const float* x2    = (const float*)d_in[1];
    const float* W1    = (const float*)d_in[2];
    const float* W2    = (const float*)d_in[3];
    const float* Wp    = (const float*)d_in[4];
    const float* gamma = (const float*)d_in[5];
    const float* beta  = (const float*)d_in[6];
    float* out = (float*)d_out;

    static bool attr_done = false;
    if (!attr_done) {
        cudaFuncSetAttribute(bilinear_mma_kernel,
                             cudaFuncAttributeMaxDynamicSharedMemorySize, SMEM_TOTAL);
        attr_done = true;
    }

    wsplit_kernel<<<(OUTC * KTOT) / 256, 256>>>(Wp);
    proj_kernel<<<NPIX / 64, 256>>>(x1, W1, 0);
    proj_kernel<<<NPIX / 64, 256>>>(x2, W2, 1);
    bilinear_mma_kernel<<<NPIX / 128, 512, SMEM_TOTAL>>>(gamma, beta, out);
}

// round 4
// speedup vs baseline: 3.1254x; 1.8549x over previous
#include <cuda_runtime.h>
#include <cuda_fp16.h>
#include <cstdint>
#include <math.h>

// Problem constants
#define BATCH 8
#define CIN   128
#define HW    3136        // 56*56
#define NPIX  25088       // 8*3136
#define MID   64
#define OUTC  256
#define KTOT  4096        // 64*64
#define EPS   1e-5f

// Scratch (device globals: allocation-free rule)
__device__ __align__(16) float g_p1[(size_t)MID * NPIX];     // [m][pix]
__device__ __align__(16) float g_p2[(size_t)MID * NPIX];     // [d][pix]
__device__ __align__(16) __half g_Wh[(size_t)OUTC * KTOT];   // fp16 Wp, native [o][k] layout

// ---------------------------------------------------------------------------
// Helpers (arch-portable PTX only: cp.async / ldmatrix / mma.sync)
// ---------------------------------------------------------------------------
__device__ __forceinline__ uint32_t smem_u32(const void* p) {
    uint32_t a;
    asm("{ .reg .u64 t; cvta.to.shared.u64 t, %1; cvt.u32.u64 %0, t; }" : "=r"(a) : "l"(p));
    return a;
}
__device__ __forceinline__ void cp16(uint32_t dst, const void* src) {
    asm volatile("cp.async.cg.shared.global [%0], [%1], 16;\n" :: "r"(dst), "l"(src));
}
#define CP_COMMIT() asm volatile("cp.async.commit_group;\n" ::: "memory")
#define CP_WAIT0()  asm volatile("cp.async.wait_group 0;\n" ::: "memory")

__device__ __forceinline__ void ldsm_x4(uint32_t& r0, uint32_t& r1, uint32_t& r2, uint32_t& r3,
                                        uint32_t addr) {
    asm volatile("ldmatrix.sync.aligned.m8n8.x4.shared.b16 {%0,%1,%2,%3}, [%4];"
                 : "=r"(r0), "=r"(r1), "=r"(r2), "=r"(r3) : "r"(addr));
}
__device__ __forceinline__ void mma16816(float* c, const uint32_t* a, const uint32_t* b) {
    asm volatile(
        "mma.sync.aligned.m16n8k16.row.col.f32.f16.f16.f32 "
        "{%0,%1,%2,%3}, {%4,%5,%6,%7}, {%8,%9}, {%0,%1,%2,%3};"
        : "+f"(c[0]), "+f"(c[1]), "+f"(c[2]), "+f"(c[3])
        : "r"(a[0]), "r"(a[1]), "r"(a[2]), "r"(a[3]), "r"(b[0]), "r"(b[1]));
}

#define SWZ(off) ((off) ^ (((off) >> 3) & 0x70))

// ---------------------------------------------------------------------------
// SMEM layout (bytes). Tiles are rows of 128B (64 fp16), SW128-swizzled.
// Double-buffered A (hi+lo) and B.
// ---------------------------------------------------------------------------
#define OFF_P1   0          // p1 tile [c][pix] 64x128 fp32 = 32768
#define OFF_A0   32768      // stage0: Ah 16384 then Al 16384
#define OFF_A1   65536      // stage1
#define OFF_B0   98304      // B stage0 256x64 fp16 = 32768
#define OFF_B1   131072
#define OFF_GB   163840     // gamma 256 + beta 256 fp32 = 2048
#define SMEM_TOTAL 165888
// Epilogue D tile reuses [0, 132096): 128 rows x 258 fp32 (padded stride)
#define DSTRIDE  258

// ---------------------------------------------------------------------------
// Wp -> fp16 (native [o][k] layout preserved)
// ---------------------------------------------------------------------------
__global__ void wsplit_kernel(const float* __restrict__ Wp) {
    int idx = blockIdx.x * 256 + threadIdx.x;
    g_Wh[idx] = __float2half_rn(Wp[idx]);
}

// ---------------------------------------------------------------------------
// Projection: p[m][pix] = sum_c W[m][c] * x[b][c][hw]   (validated R1/R3)
// ---------------------------------------------------------------------------
__global__ __launch_bounds__(256)
void proj_kernel(const float* __restrict__ x, const float* __restrict__ Wm, int which) {
    __shared__ float Ws[CIN][MID];
    float* p = which ? g_p2 : g_p1;

    int t = threadIdx.x;
    for (int idx = t; idx < MID * CIN; idx += 256) {
        int c = idx >> 6;
        int m = idx & 63;
        Ws[c][m] = __ldg(&Wm[m * CIN + c]);
    }
    __syncthreads();

    int pixg0 = blockIdx.x * 64;
    int b   = pixg0 / HW;
    int hw0 = pixg0 - b * HW;

    int tx = t & 15;
    int ty = t >> 4;

    const float* xb = x + (size_t)b * CIN * HW + hw0 + tx * 4;

    float acc[4][4];
#pragma unroll
    for (int mi = 0; mi < 4; mi++)
#pragma unroll
        for (int pi = 0; pi < 4; pi++) acc[mi][pi] = 0.0f;

#pragma unroll 4
    for (int c = 0; c < CIN; c++) {
        float4 xv = *(const float4*)(xb + (size_t)c * HW);
        float4 wv = *(const float4*)&Ws[c][ty * 4];
        float xs[4] = {xv.x, xv.y, xv.z, xv.w};
        float wsv[4] = {wv.x, wv.y, wv.z, wv.w};
#pragma unroll
        for (int mi = 0; mi < 4; mi++)
#pragma unroll
            for (int pi = 0; pi < 4; pi++)
                acc[mi][pi] += wsv[mi] * xs[pi];
    }

#pragma unroll
    for (int mi = 0; mi < 4; mi++) {
        float4 v = make_float4(acc[mi][0], acc[mi][1], acc[mi][2], acc[mi][3]);
        *(float4*)(p + (size_t)(ty * 4 + mi) * NPIX + pixg0 + tx * 4) = v;
    }
}

// ---------------------------------------------------------------------------
// Main: mma.sync fp16 (A hi/lo, B single) GEMM + LN + exact GELU
// CTA: 128 pix x 256 o, K=4096. 512 threads = 16 warps (4 pix x 4 o groups).
// Warp tile: 32 pix x 64 o -> 64 fp32 accum regs/thread. One barrier/chunk.
// ---------------------------------------------------------------------------
__global__ __launch_bounds__(512, 1)
void bilinear_mma_kernel(const float* __restrict__ gamma,
                         const float* __restrict__ beta,
                         float* __restrict__ out) {
    extern __shared__ char smem[];
    const uint32_t sbase = smem_u32(smem);

    const int t   = threadIdx.x;
    const int wid = t >> 5;
    const int lid = t & 31;
    const int wp  = wid >> 2;   // pixel group: rows wp*32
    const int wo  = wid & 3;    // o group: cols wo*64
    const int pix0 = blockIdx.x * 128;

    // gamma/beta to smem
    {
        float* gb = (float*)(smem + OFF_GB);
        if (t < 256) gb[t] = __ldg(&gamma[t]);
        else gb[256 + (t - 256)] = __ldg(&beta[t - 256]);
    }

    // p1 tile -> smem  [c][128 pix]
    float* p1s = (float*)(smem + OFF_P1);
#pragma unroll
    for (int r = 0; r < 16; r++) {
        int i = t + r * 512;
        int c = i >> 7, px = i & 127;
        p1s[i] = g_p1[(size_t)c * NPIX + pix0 + px];
    }

    // p2 quarter-row in registers: thread owns pixel t>>2, d-range (t&3)*16..+15
    const int apix = t >> 2;
    const int aq   = t & 3;
    float p2r[16];
#pragma unroll
    for (int j = 0; j < 16; j++)
        p2r[j] = g_p2[(size_t)(aq * 16 + j) * NPIX + pix0 + apix];

    const uint32_t offA[2] = {OFF_A0, OFF_A1};
    const uint32_t offB[2] = {OFF_B0, OFF_B1};

    // ---- A-build lambda-ish macro: build chunk ch into stage st ----
    // a[pix][d] = p1[pix][ch] * p2[pix][d]; fp16 hi in [0,16K), lo in [16K,32K)
    auto build_A = [&](int ch, int st) {
        const float p1v = p1s[ch * 128 + apix];
        char* ah = smem + offA[st];
        char* al = ah + 16384;
#pragma unroll
        for (int jj = 0; jj < 8; jj++) {
            float a0 = p1v * p2r[2 * jj];
            float a1 = p1v * p2r[2 * jj + 1];
            __half2 h2 = __floats2half2_rn(a0, a1);          // x=a0(lo), y=a1(hi)
            float r0 = a0 - __half2float(__low2half(h2));
            float r1 = a1 - __half2float(__high2half(h2));
            __half2 l2 = __floats2half2_rn(r0, r1);
            uint32_t boff = SWZ((uint32_t)(apix * 128 + (aq * 16 + 2 * jj) * 2));
            *(__half2*)(ah + boff) = h2;
            *(__half2*)(al + boff) = l2;
        }
    };
    auto fetch_B = [&](int ch, int st) {
        const __half* bh = g_Wh + (size_t)ch * 64;
#pragma unroll
        for (int r = 0; r < 4; r++) {
            int idx = t + r * 512;       // 0..2047
            int o   = idx >> 3;
            int seg = idx & 7;
            uint32_t doff = SWZ((uint32_t)(o * 128 + seg * 16));
            cp16(sbase + offB[st] + doff, bh + (size_t)o * KTOT + seg * 8);
        }
        CP_COMMIT();
    };

    float acc[2][8][4];
#pragma unroll
    for (int mt = 0; mt < 2; mt++)
#pragma unroll
        for (int nt = 0; nt < 8; nt++)
#pragma unroll
            for (int i = 0; i < 4; i++) acc[mt][nt][i] = 0.0f;

    // Prologue: publish stage 0 (chunk 0)
    fetch_B(0, 0);
    __syncthreads();            // p1s visible for build_A
    build_A(0, 0);
    CP_WAIT0();
    __syncthreads();            // stage 0 published

    // Per-lane ldmatrix row components (swizzle applied per use)
    const int a_row_l = lid & 15;
    const int a_hi16  = (lid >> 4) * 16;
    const int b_row_l = ((lid >> 4) << 3) + (lid & 7);
    const int b_hi16  = ((lid >> 3) & 1) * 16;

    for (int ch = 0; ch < 64; ch++) {
        const int s = ch & 1;

        // stage s^1: prefetch B(ch+1) + build A(ch+1) (no conflict with readers of s)
        if (ch < 63) {
            fetch_B(ch + 1, s ^ 1);
            build_A(ch + 1, s ^ 1);
        }

        // MMA on stage s: B loaded once per kk, reused for Ah and Al passes
        const uint32_t ab = sbase + offA[s];
        const uint32_t bb = sbase + offB[s];
#pragma unroll
        for (int kk = 0; kk < 4; kk++) {
            // B fragments: 8 n-tiles via 4 x4-ldmatrix
            uint32_t bfr[8][2];
#pragma unroll
            for (int bp = 0; bp < 4; bp++) {
                int orow = wo * 64 + bp * 16 + b_row_l;
                uint32_t addr = bb + SWZ((uint32_t)(orow * 128 + kk * 32 + b_hi16));
                uint32_t r0, r1, r2, r3;
                ldsm_x4(r0, r1, r2, r3, addr);
                bfr[bp * 2][0] = r0;      bfr[bp * 2][1] = r1;
                bfr[bp * 2 + 1][0] = r2;  bfr[bp * 2 + 1][1] = r3;
            }
            // Pass hi then lo, sharing bfr
#pragma unroll
            for (int pass = 0; pass < 2; pass++) {
                const uint32_t abase = ab + pass * 16384;
                uint32_t afr[2][4];
#pragma unroll
                for (int mt = 0; mt < 2; mt++) {
                    int row = wp * 32 + mt * 16 + a_row_l;
                    uint32_t addr = abase + SWZ((uint32_t)(row * 128 + kk * 32 + a_hi16));
                    ldsm_x4(afr[mt][0], afr[mt][1], afr[mt][2], afr[mt][3], addr);
                }
#pragma unroll
                for (int mt = 0; mt < 2; mt++)
#pragma unroll
                    for (int nt = 0; nt < 8; nt++)
                        mma16816(acc[mt][nt], afr[mt], bfr[nt]);
            }
        }

        if (ch < 63) CP_WAIT0();
        __syncthreads();   // stage s consumed; stage s^1 published
    }

    // --- epilogue: acc -> smem D, per-pixel LN + GELU + store ---
    float* D = (float*)smem;   // reuses p1s/A/B region (all dead; synced above)
#pragma unroll
    for (int mt = 0; mt < 2; mt++) {
#pragma unroll
        for (int nt = 0; nt < 8; nt++) {
            int row = wp * 32 + mt * 16 + (lid >> 2);
            int col = wo * 64 + nt * 8 + (lid & 3) * 2;
            *(float2*)&D[row * DSTRIDE + col] = make_float2(acc[mt][nt][0], acc[mt][nt][1]);
            *(float2*)&D[(row + 8) * DSTRIDE + col] = make_float2(acc[mt][nt][2], acc[mt][nt][3]);
        }
    }
    __syncthreads();

    {
        const int pix = t >> 2;
        const int q   = t & 3;
        const float* Drow = D + pix * DSTRIDE + q * 64;
        float s1 = 0.0f, s2 = 0.0f;
#pragma unroll
        for (int j = 0; j < 32; j++) {
            float2 v = *(const float2*)&Drow[j * 2];
            s1 += v.x + v.y;
            s2 += v.x * v.x + v.y * v.y;
        }
        // quad reduce
        s1 += __shfl_xor_sync(0xffffffffu, s1, 1);
        s2 += __shfl_xor_sync(0xffffffffu, s2, 1);
        s1 += __shfl_xor_sync(0xffffffffu, s1, 2);
        s2 += __shfl_xor_sync(0xffffffffu, s2, 2);

        float mu = s1 * (1.0f / OUTC);
        float var = s2 * (1.0f / OUTC) - mu * mu;
        float rs = rsqrtf(var + EPS);

        const int P  = pix0 + pix;
        const int bb = P / HW;
        const int hw = P - bb * HW;
        float* obase = out + (size_t)bb * OUTC * HW + hw;
        const float* sg  = (const float*)(smem + OFF_GB);
        const float* sbt = sg + 256;

#pragma unroll
        for (int j = 0; j < 64; j++) {
            int o = q * 64 + j;
            float x = (Drow[j] - mu) * rs * sg[o] + sbt[o];
            float y = 0.5f * x * (1.0f + erff(x * 0.70710678118654752f));
            obase[(size_t)o * HW] = y;
        }
    }
}

// ---------------------------------------------------------------------------
extern "C" void kernel_launch(void* const* d_in, const int* in_sizes, int n_in,
                              void* d_out, int out_size) {
    const float* x1    = (const float*)d_in[0];
    const float* x2    = (const float*)d_in[1];
    const float* W1    = (const float*)d_in[2];
    const float* W2    = (const float*)d_in[3];
    const float* Wp    = (const float*)d_in[4];
    const float* gamma = (const float*)d_in[5];
    const float* beta  = (const float*)d_in[6];
    float* out = (float*)d_out;

    static bool attr_done = false;
    if (!attr_done) {
        cudaFuncSetAttribute(bilinear_mma_kernel,
                             cudaFuncAttributeMaxDynamicSharedMemorySize, SMEM_TOTAL);
        attr_done = true;
    }

    wsplit_kernel<<<(OUTC * KTOT) / 256, 256>>>(Wp);
    proj_kernel<<<NPIX / 64, 256>>>(x1, W1, 0);
    proj_kernel<<<NPIX / 64, 256>>>(x2, W2, 1);
    bilinear_mma_kernel<<<NPIX / 128, 512, SMEM_TOTAL>>>(gamma, beta, out);
}

// round 5
// speedup vs baseline: 5.7213x; 1.8306x over previous
#include <cuda_runtime.h>
#include <cuda_fp16.h>
#include <cstdint>
#include <math.h>

// Problem constants
#define BATCH 8
#define CIN   128
#define HW    3136        // 56*56
#define NPIX  25088       // 8*3136
#define MID   64
#define OUTC  256
#define KTOT  4096        // 64*64
#define EPS   1e-5f

// Scratch (device globals: allocation-free rule)
__device__ __align__(16) float g_p1[(size_t)MID * NPIX];     // [m][pix]
__device__ __align__(16) float g_p2[(size_t)MID * NPIX];     // [d][pix]
__device__ __align__(16) __half g_Wh[(size_t)OUTC * KTOT];   // fp16 Wp, native [o][k] layout

// ---------------------------------------------------------------------------
// Helpers (arch-portable PTX only: cp.async / ldmatrix / mma.sync)
// ---------------------------------------------------------------------------
__device__ __forceinline__ uint32_t smem_u32(const void* p) {
    uint32_t a;
    asm("{ .reg .u64 t; cvta.to.shared.u64 t, %1; cvt.u32.u64 %0, t; }" : "=r"(a) : "l"(p));
    return a;
}
__device__ __forceinline__ void cp16(uint32_t dst, const void* src) {
    asm volatile("cp.async.cg.shared.global [%0], [%1], 16;\n" :: "r"(dst), "l"(src));
}
#define CP_COMMIT() asm volatile("cp.async.commit_group;\n" ::: "memory")
#define CP_WAIT0()  asm volatile("cp.async.wait_group 0;\n" ::: "memory")

__device__ __forceinline__ void ldsm_x4(uint32_t& r0, uint32_t& r1, uint32_t& r2, uint32_t& r3,
                                        uint32_t addr) {
    asm volatile("ldmatrix.sync.aligned.m8n8.x4.shared.b16 {%0,%1,%2,%3}, [%4];"
                 : "=r"(r0), "=r"(r1), "=r"(r2), "=r"(r3) : "r"(addr));
}
__device__ __forceinline__ void mma16816(float* c, const uint32_t* a, const uint32_t* b) {
    asm volatile(
        "mma.sync.aligned.m16n8k16.row.col.f32.f16.f16.f32 "
        "{%0,%1,%2,%3}, {%4,%5,%6,%7}, {%8,%9}, {%0,%1,%2,%3};"
        : "+f"(c[0]), "+f"(c[1]), "+f"(c[2]), "+f"(c[3])
        : "r"(a[0]), "r"(a[1]), "r"(a[2]), "r"(a[3]), "r"(b[0]), "r"(b[1]));
}

#define SWZ(off) ((off) ^ (((off) >> 3) & 0x70))

// ---------------------------------------------------------------------------
// SMEM layout (per CTA, bytes). Rows of 128B (64 fp16), SW128-swizzled tiles.
// CTA tile: 64 pix x 256 o. 2 CTAs/SM.
// ---------------------------------------------------------------------------
#define OFF_P1   0          // p1 tile [c][pix] 64x64 fp32 = 16384
#define OFF_A0   16384      // A stage0: 64pix x 64d fp16 = 8192
#define OFF_A1   24576
#define OFF_B0   32768      // B stage0: 256o x 64d fp16 = 32768
#define OFF_B1   65536
#define OFF_GB   98304      // gamma 256 + beta 256 fp32 = 2048
#define SMEM_TOTAL 100352
// Epilogue D tile reuses [0, 66048): 64 rows x 258 fp32 (padded stride)
#define DSTRIDE  258

// ---------------------------------------------------------------------------
// Wp -> fp16 (native [o][k] layout preserved)
// ---------------------------------------------------------------------------
__global__ void wsplit_kernel(const float* __restrict__ Wp) {
    int idx = blockIdx.x * 256 + threadIdx.x;
    g_Wh[idx] = __float2half_rn(Wp[idx]);
}

// ---------------------------------------------------------------------------
// Projection: p[m][pix] = sum_c W[m][c] * x[b][c][hw]
// Fused: blockIdx.y selects (x1,W1)->g_p1 vs (x2,W2)->g_p2.
// ---------------------------------------------------------------------------
__global__ __launch_bounds__(256)
void proj_kernel(const float* __restrict__ x1v, const float* __restrict__ x2v,
                 const float* __restrict__ W1v, const float* __restrict__ W2v) {
    __shared__ float Ws[CIN][MID];
    const int which = blockIdx.y;
    const float* x  = which ? x2v : x1v;
    const float* Wm = which ? W2v : W1v;
    float* p = which ? g_p2 : g_p1;

    int t = threadIdx.x;
    for (int idx = t; idx < MID * CIN; idx += 256) {
        int c = idx >> 6;
        int m = idx & 63;
        Ws[c][m] = __ldg(&Wm[m * CIN + c]);
    }
    __syncthreads();

    int pixg0 = blockIdx.x * 64;
    int b   = pixg0 / HW;
    int hw0 = pixg0 - b * HW;

    int tx = t & 15;
    int ty = t >> 4;

    const float* xb = x + (size_t)b * CIN * HW + hw0 + tx * 4;

    float acc[4][4];
#pragma unroll
    for (int mi = 0; mi < 4; mi++)
#pragma unroll
        for (int pi = 0; pi < 4; pi++) acc[mi][pi] = 0.0f;

#pragma unroll 4
    for (int c = 0; c < CIN; c++) {
        float4 xv = *(const float4*)(xb + (size_t)c * HW);
        float4 wv = *(const float4*)&Ws[c][ty * 4];
        float xs[4] = {xv.x, xv.y, xv.z, xv.w};
        float wsv[4] = {wv.x, wv.y, wv.z, wv.w};
#pragma unroll
        for (int mi = 0; mi < 4; mi++)
#pragma unroll
            for (int pi = 0; pi < 4; pi++)
                acc[mi][pi] += wsv[mi] * xs[pi];
    }

#pragma unroll
    for (int mi = 0; mi < 4; mi++) {
        float4 v = make_float4(acc[mi][0], acc[mi][1], acc[mi][2], acc[mi][3]);
        *(float4*)(p + (size_t)(ty * 4 + mi) * NPIX + pixg0 + tx * 4) = v;
    }
}

// ---------------------------------------------------------------------------
// Main: mma.sync fp16 single-pass GEMM + LN + exact GELU
// CTA: 64 pix x 256 o, K=4096. 256 threads = 8 warps (2 pix x 4 o groups).
// Warp tile: 32 pix x 64 o -> 64 fp32 accum regs/thread. 2 CTAs/SM.
// ---------------------------------------------------------------------------
__global__ __launch_bounds__(256, 2)
void bilinear_mma_kernel(const float* __restrict__ gamma,
                         const float* __restrict__ beta,
                         float* __restrict__ out) {
    extern __shared__ char smem[];
    const uint32_t sbase = smem_u32(smem);

    const int t   = threadIdx.x;
    const int wid = t >> 5;
    const int lid = t & 31;
    const int wp  = wid >> 2;   // pixel group: rows wp*32   (0..1)
    const int wo  = wid & 3;    // o group: cols wo*64       (0..3)
    const int pix0 = blockIdx.x * 64;

    // gamma/beta to smem
    {
        float* gb = (float*)(smem + OFF_GB);
        gb[t]       = __ldg(&gamma[t]);
        gb[256 + t] = __ldg(&beta[t]);
    }

    // p1 tile -> smem  [c][64 pix]
    float* p1s = (float*)(smem + OFF_P1);
#pragma unroll
    for (int r = 0; r < 16; r++) {
        int i = t + r * 256;
        int c = i >> 6, px = i & 63;
        p1s[i] = g_p1[(size_t)c * NPIX + pix0 + px];
    }

    // p2 quarter-row in registers: thread owns pixel t>>2, d-range (t&3)*16..+15
    const int apix = t >> 2;
    const int aq   = t & 3;
    float p2r[16];
#pragma unroll
    for (int j = 0; j < 16; j++)
        p2r[j] = g_p2[(size_t)(aq * 16 + j) * NPIX + pix0 + apix];

    const uint32_t offA[2] = {OFF_A0, OFF_A1};
    const uint32_t offB[2] = {OFF_B0, OFF_B1};

    // build chunk ch into stage st: a[pix][d] = p1[pix][ch] * p2[pix][d], fp16
    auto build_A = [&](int ch, int st) {
        const float p1v = p1s[ch * 64 + apix];
        char* ah = smem + offA[st];
#pragma unroll
        for (int jj = 0; jj < 8; jj++) {
            float a0 = p1v * p2r[2 * jj];
            float a1 = p1v * p2r[2 * jj + 1];
            __half2 h2 = __floats2half2_rn(a0, a1);
            uint32_t boff = SWZ((uint32_t)(apix * 128 + (aq * 16 + 2 * jj) * 2));
            *(__half2*)(ah + boff) = h2;
        }
    };
    auto fetch_B = [&](int ch, int st) {
        const __half* bh = g_Wh + (size_t)ch * 64;
#pragma unroll
        for (int r = 0; r < 8; r++) {
            int idx = t + r * 256;       // 0..2047
            int o   = idx >> 3;
            int seg = idx & 7;
            uint32_t doff = SWZ((uint32_t)(o * 128 + seg * 16));
            cp16(sbase + offB[st] + doff, bh + (size_t)o * KTOT + seg * 8);
        }
        CP_COMMIT();
    };

    float acc[2][8][4];
#pragma unroll
    for (int mt = 0; mt < 2; mt++)
#pragma unroll
        for (int nt = 0; nt < 8; nt++)
#pragma unroll
            for (int i = 0; i < 4; i++) acc[mt][nt][i] = 0.0f;

    // Prologue: publish stage 0 (chunk 0)
    fetch_B(0, 0);
    __syncthreads();            // p1s visible for build_A
    build_A(0, 0);
    CP_WAIT0();
    __syncthreads();            // stage 0 published

    // Per-lane ldmatrix row components (swizzle applied per use)
    const int a_row_l = lid & 15;
    const int a_hi16  = (lid >> 4) * 16;
    const int b_row_l = ((lid >> 4) << 3) + (lid & 7);
    const int b_hi16  = ((lid >> 3) & 1) * 16;

    for (int ch = 0; ch < 64; ch++) {
        const int s = ch & 1;

        // stage s^1: prefetch B(ch+1) + build A(ch+1)
        if (ch < 63) {
            fetch_B(ch + 1, s ^ 1);
            build_A(ch + 1, s ^ 1);
        }

        // MMA on stage s
        const uint32_t ab = sbase + offA[s];
        const uint32_t bb = sbase + offB[s];
#pragma unroll
        for (int kk = 0; kk < 4; kk++) {
            // B fragments: 8 n-tiles via 4 x4-ldmatrix
            uint32_t bfr[8][2];
#pragma unroll
            for (int bp = 0; bp < 4; bp++) {
                int orow = wo * 64 + bp * 16 + b_row_l;
                uint32_t addr = bb + SWZ((uint32_t)(orow * 128 + kk * 32 + b_hi16));
                uint32_t r0, r1, r2, r3;
                ldsm_x4(r0, r1, r2, r3, addr);
                bfr[bp * 2][0] = r0;      bfr[bp * 2][1] = r1;
                bfr[bp * 2 + 1][0] = r2;  bfr[bp * 2 + 1][1] = r3;
            }
            // A fragments: 2 m-tiles
            uint32_t afr[2][4];
#pragma unroll
            for (int mt = 0; mt < 2; mt++) {
                int row = wp * 32 + mt * 16 + a_row_l;
                uint32_t addr = ab + SWZ((uint32_t)(row * 128 + kk * 32 + a_hi16));
                ldsm_x4(afr[mt][0], afr[mt][1], afr[mt][2], afr[mt][3], addr);
            }
#pragma unroll
            for (int mt = 0; mt < 2; mt++)
#pragma unroll
                for (int nt = 0; nt < 8; nt++)
                    mma16816(acc[mt][nt], afr[mt], bfr[nt]);
        }

        if (ch < 63) CP_WAIT0();
        __syncthreads();   // stage s consumed; stage s^1 published
    }

    // --- epilogue: acc -> smem D, per-pixel LN + GELU + store ---
    float* D = (float*)smem;   // reuses p1s/A/B region (all dead; synced above)
#pragma unroll
    for (int mt = 0; mt < 2; mt++) {
#pragma unroll
        for (int nt = 0; nt < 8; nt++) {
            int row = wp * 32 + mt * 16 + (lid >> 2);
            int col = wo * 64 + nt * 8 + (lid & 3) * 2;
            *(float2*)&D[row * DSTRIDE + col] = make_float2(acc[mt][nt][0], acc[mt][nt][1]);
            *(float2*)&D[(row + 8) * DSTRIDE + col] = make_float2(acc[mt][nt][2], acc[mt][nt][3]);
        }
    }
    __syncthreads();

    {
        const int pix = t >> 2;   // 0..63
        const int q   = t & 3;
        const float* Drow = D + pix * DSTRIDE + q * 64;
        float s1 = 0.0f, s2 = 0.0f;
#pragma unroll
        for (int j = 0; j < 32; j++) {
            float2 v = *(const float2*)&Drow[j * 2];
            s1 += v.x + v.y;
            s2 += v.x * v.x + v.y * v.y;
        }
        // quad reduce
        s1 += __shfl_xor_sync(0xffffffffu, s1, 1);
        s2 += __shfl_xor_sync(0xffffffffu, s2, 1);
        s1 += __shfl_xor_sync(0xffffffffu, s1, 2);
        s2 += __shfl_xor_sync(0xffffffffu, s2, 2);

        float mu = s1 * (1.0f / OUTC);
        float var = s2 * (1.0f / OUTC) - mu * mu;
        float rs = rsqrtf(var + EPS);

        const int P  = pix0 + pix;
        const int bb = P / HW;
        const int hw = P - bb * HW;
        float* obase = out + (size_t)bb * OUTC * HW + hw;
        const float* sg  = (const float*)(smem + OFF_GB);
        const float* sbt = sg + 256;

#pragma unroll
        for (int j = 0; j < 64; j++) {
            int o = q * 64 + j;
            float x = (Drow[j] - mu) * rs * sg[o] + sbt[o];
            float y = 0.5f * x * (1.0f + erff(x * 0.70710678118654752f));
            obase[(size_t)o * HW] = y;
        }
    }
}

// ---------------------------------------------------------------------------
extern "C" void kernel_launch(void* const* d_in, const int* in_sizes, int n_in,
                              void* d_out, int out_size) {
    const float* x1    = (const float*)d_in[0];
    const float* x2    = (const float*)d_in[1];
    const float* W1    = (const float*)d_in[2];
    const float* W2    = (const float*)d_in[3];
    const float* Wp    = (const float*)d_in[4];
    const float* gamma = (const float*)d_in[5];
    const float* beta  = (const float*)d_in[6];
    float* out = (float*)d_out;

    static bool attr_done = false;
    if (!attr_done) {
        cudaFuncSetAttribute(bilinear_mma_kernel,
                             cudaFuncAttributeMaxDynamicSharedMemorySize, SMEM_TOTAL);
        attr_done = true;
    }

    wsplit_kernel<<<(OUTC * KTOT) / 256, 256>>>(Wp);
    proj_kernel<<<dim3(NPIX / 64, 2), 256>>>(x1, x2, W1, W2);
    bilinear_mma_kernel<<<NPIX / 64, 256, SMEM_TOTAL>>>(gamma, beta, out);
}

// round 7
// speedup vs baseline: 5.9745x; 1.0443x over previous
#include <cuda_runtime.h>
#include <cuda_fp16.h>
#include <cstdint>
#include <math.h>

// Problem constants
#define BATCH 8
#define CIN   128
#define HW    3136        // 56*56
#define NPIX  25088       // 8*3136
#define MID   64
#define OUTC  256
#define KTOT  4096        // 64*64
#define EPS   1e-5f

// Scratch (device globals: allocation-free rule)
__device__ __align__(16) float g_p1[(size_t)MID * NPIX];     // [m][pix]
__device__ __align__(16) float g_p2t[(size_t)NPIX * MID];    // [pix][d]  (transposed)
__device__ __align__(16) __half g_Wh[(size_t)OUTC * KTOT];   // fp16 Wp, native [o][k] layout

// ---------------------------------------------------------------------------
// Helpers (arch-portable PTX only: cp.async / ldmatrix / mma.sync)
// ---------------------------------------------------------------------------
__device__ __forceinline__ uint32_t smem_u32(const void* p) {
    uint32_t a;
    asm("{ .reg .u64 t; cvta.to.shared.u64 t, %1; cvt.u32.u64 %0, t; }" : "=r"(a) : "l"(p));
    return a;
}
__device__ __forceinline__ uint32_t h2_u32(__half2 h) {
    union { __half2 h; uint32_t u; } cv;
    cv.h = h;
    return cv.u;
}
__device__ __forceinline__ __half2 u32_h2(uint32_t u) {
    union { __half2 h; uint32_t u; } cv;
    cv.u = u;
    return cv.h;
}
__device__ __forceinline__ void cp16(uint32_t dst, const void* src) {
    asm volatile("cp.async.cg.shared.global [%0], [%1], 16;\n" :: "r"(dst), "l"(src));
}
#define CP_COMMIT() asm volatile("cp.async.commit_group;\n" ::: "memory")
#define CP_WAIT0()  asm volatile("cp.async.wait_group 0;\n" ::: "memory")

__device__ __forceinline__ void ldsm_x4(uint32_t& r0, uint32_t& r1, uint32_t& r2, uint32_t& r3,
                                        uint32_t addr) {
    asm volatile("ldmatrix.sync.aligned.m8n8.x4.shared.b16 {%0,%1,%2,%3}, [%4];"
                 : "=r"(r0), "=r"(r1), "=r"(r2), "=r"(r3) : "r"(addr));
}
__device__ __forceinline__ void mma16816(float* c, const uint32_t* a, uint32_t b0, uint32_t b1) {
    asm volatile(
        "mma.sync.aligned.m16n8k16.row.col.f32.f16.f16.f32 "
        "{%0,%1,%2,%3}, {%4,%5,%6,%7}, {%8,%9}, {%0,%1,%2,%3};"
        : "+f"(c[0]), "+f"(c[1]), "+f"(c[2]), "+f"(c[3])
        : "r"(a[0]), "r"(a[1]), "r"(a[2]), "r"(a[3]), "r"(b0), "r"(b1));
}

#define SWZ(off) ((off) ^ (((off) >> 3) & 0x70))

// ---------------------------------------------------------------------------
// SMEM layout (per CTA, bytes). CTA tile: 64 pix x 256 o. 2 CTAs/SM.
// ---------------------------------------------------------------------------
#define OFF_P1   0          // p1 tile [c][pix] 64x64 fp32 = 16384
#define OFF_B0   16384      // B stage0: 256o x 64d fp16 = 32768 (SW128)
#define OFF_B1   49152
#define OFF_GB   81920      // gamma 256 + beta 256 fp32 = 2048
#define SMEM_TOTAL 83968
// Epilogue D tile reuses [0, 66048): 64 rows x 258 fp32 (padded stride)
#define DSTRIDE  258

// ---------------------------------------------------------------------------
// Wp -> fp16 (native [o][k] layout preserved)
// ---------------------------------------------------------------------------
__global__ void wsplit_kernel(const float* __restrict__ Wp) {
    int idx = blockIdx.x * 256 + threadIdx.x;
    g_Wh[idx] = __float2half_rn(Wp[idx]);
}

// ---------------------------------------------------------------------------
// Projection: p[m][pix] = sum_c W[m][c] * x[b][c][hw]
// which=0 -> g_p1 [m][pix];  which=1 -> g_p2t [pix][d] (transposed store)
// ---------------------------------------------------------------------------
__global__ __launch_bounds__(256)
void proj_kernel(const float* __restrict__ x1v, const float* __restrict__ x2v,
                 const float* __restrict__ W1v, const float* __restrict__ W2v) {
    __shared__ float Ws[CIN][MID];
    const int which = blockIdx.y;
    const float* x  = which ? x2v : x1v;
    const float* Wm = which ? W2v : W1v;

    int t = threadIdx.x;
    for (int idx = t; idx < MID * CIN; idx += 256) {
        int c = idx >> 6;
        int m = idx & 63;
        Ws[c][m] = __ldg(&Wm[m * CIN + c]);
    }
    __syncthreads();

    int pixg0 = blockIdx.x * 64;
    int b   = pixg0 / HW;
    int hw0 = pixg0 - b * HW;

    int tx = t & 15;
    int ty = t >> 4;

    const float* xb = x + (size_t)b * CIN * HW + hw0 + tx * 4;

    float acc[4][4];
#pragma unroll
    for (int mi = 0; mi < 4; mi++)
#pragma unroll
        for (int pi = 0; pi < 4; pi++) acc[mi][pi] = 0.0f;

#pragma unroll 4
    for (int c = 0; c < CIN; c++) {
        float4 xv = *(const float4*)(xb + (size_t)c * HW);
        float4 wv = *(const float4*)&Ws[c][ty * 4];
        float xs[4] = {xv.x, xv.y, xv.z, xv.w};
        float wsv[4] = {wv.x, wv.y, wv.z, wv.w};
#pragma unroll
        for (int mi = 0; mi < 4; mi++)
#pragma unroll
            for (int pi = 0; pi < 4; pi++)
                acc[mi][pi] += wsv[mi] * xs[pi];
    }

    if (which == 0) {
#pragma unroll
        for (int mi = 0; mi < 4; mi++) {
            float4 v = make_float4(acc[mi][0], acc[mi][1], acc[mi][2], acc[mi][3]);
            *(float4*)(g_p1 + (size_t)(ty * 4 + mi) * NPIX + pixg0 + tx * 4) = v;
        }
    } else {
        // transposed: g_p2t[pix][d], d = ty*4..+3 contiguous
#pragma unroll
        for (int pi = 0; pi < 4; pi++) {
            float4 v = make_float4(acc[0][pi], acc[1][pi], acc[2][pi], acc[3][pi]);
            *(float4*)(g_p2t + (size_t)(pixg0 + tx * 4 + pi) * MID + ty * 4) = v;
        }
    }
}

// ---------------------------------------------------------------------------
// Main: mma.sync fp16, A fragment built in registers (p2 persistent in frag
// layout, scaled per chunk by p1 scalar). B streamed via cp.async (2-stage).
// CTA: 64 pix x 256 o, K=4096. 256 threads = 8 warps (2 pix x 4 o groups).
// ---------------------------------------------------------------------------
__global__ __launch_bounds__(256, 2)
void bilinear_mma_kernel(const float* __restrict__ gamma,
                         const float* __restrict__ beta,
                         float* __restrict__ out) {
    extern __shared__ char smem[];
    const uint32_t sbase = smem_u32(smem);

    const int t   = threadIdx.x;
    const int wid = t >> 5;
    const int lid = t & 31;
    const int wp  = wid >> 2;   // pixel group: rows wp*32   (0..1)
    const int wo  = wid & 3;    // o group: cols wo*64       (0..3)
    const int g   = lid >> 2;   // fragment row within 8
    const int q2  = (lid & 3) * 2;
    const int pix0 = blockIdx.x * 64;

    // gamma/beta to smem
    {
        float* gb = (float*)(smem + OFF_GB);
        gb[t]       = __ldg(&gamma[t]);
        gb[256 + t] = __ldg(&beta[t]);
    }

    // p1 tile -> smem  [c][64 pix]
    float* p1s = (float*)(smem + OFF_P1);
#pragma unroll
    for (int r = 0; r < 16; r++) {
        int i = t + r * 256;
        int c = i >> 6, px = i & 63;
        p1s[i] = g_p1[(size_t)c * NPIX + pix0 + px];
    }

    // p2 persistent fragment regs (packed half2): p2f[((mt*2+h)*4+kk)*2+j]
    //   row r = wp*32 + mt*16 + h*8 + g ; k = kk*16 + q2 + j*8 ; half2 (k, k+1)
    uint32_t p2f[32];
#pragma unroll
    for (int mt = 0; mt < 2; mt++)
#pragma unroll
        for (int h = 0; h < 2; h++) {
            const float* prow = g_p2t + (size_t)(pix0 + wp * 32 + mt * 16 + h * 8 + g) * MID;
#pragma unroll
            for (int kk = 0; kk < 4; kk++)
#pragma unroll
                for (int j = 0; j < 2; j++) {
                    float2 v = *(const float2*)&prow[kk * 16 + q2 + j * 8];
                    p2f[((mt * 2 + h) * 4 + kk) * 2 + j] =
                        h2_u32(__floats2half2_rn(v.x, v.y));
                }
        }

    const uint32_t offB[2] = {OFF_B0, OFF_B1};

    auto fetch_B = [&](int ch, int st) {
        const __half* bh = g_Wh + (size_t)ch * 64;
#pragma unroll
        for (int r = 0; r < 8; r++) {
            int idx = t + r * 256;       // 0..2047
            int o   = idx >> 3;
            int seg = idx & 7;
            uint32_t doff = SWZ((uint32_t)(o * 128 + seg * 16));
            cp16(sbase + offB[st] + doff, bh + (size_t)o * KTOT + seg * 8);
        }
        CP_COMMIT();
    };

    float acc[2][8][4];
#pragma unroll
    for (int mt = 0; mt < 2; mt++)
#pragma unroll
        for (int nt = 0; nt < 8; nt++)
#pragma unroll
            for (int i = 0; i < 4; i++) acc[mt][nt][i] = 0.0f;

    // Prologue: publish stage 0 (chunk 0)
    fetch_B(0, 0);
    CP_WAIT0();
    __syncthreads();            // stage 0 + p1s published

    const int b_row_l = ((lid >> 4) << 3) + (lid & 7);
    const int b_hi16  = ((lid >> 3) & 1) * 16;

    for (int ch = 0; ch < 64; ch++) {
        const int s = ch & 1;

        if (ch < 63) fetch_B(ch + 1, s ^ 1);

        // p1 scalars for this chunk (broadcast LDS within quads)
        float p1v[2][2];
#pragma unroll
        for (int mt = 0; mt < 2; mt++)
#pragma unroll
            for (int h = 0; h < 2; h++)
                p1v[mt][h] = p1s[ch * 64 + wp * 32 + mt * 16 + h * 8 + g];

        const uint32_t bb = sbase + offB[s];
#pragma unroll
        for (int kk = 0; kk < 4; kk++) {
            // A fragments in registers: afr[mt] = {h0j0, h1j0, h0j1, h1j1}
            uint32_t afr[2][4];
#pragma unroll
            for (int mt = 0; mt < 2; mt++)
#pragma unroll
                for (int rr = 0; rr < 4; rr++) {
                    int h = rr & 1, j = rr >> 1;
                    float2 pv = __half22float2(u32_h2(p2f[((mt * 2 + h) * 4 + kk) * 2 + j]));
                    float sc = p1v[mt][h];
                    afr[mt][rr] = h2_u32(__floats2half2_rn(sc * pv.x, sc * pv.y));
                }

            // B: load per bp and consume immediately (cap register liveness)
#pragma unroll
            for (int bp = 0; bp < 4; bp++) {
                int orow = wo * 64 + bp * 16 + b_row_l;
                uint32_t addr = bb + SWZ((uint32_t)(orow * 128 + kk * 32 + b_hi16));
                uint32_t r0, r1, r2, r3;
                ldsm_x4(r0, r1, r2, r3, addr);
                mma16816(acc[0][bp * 2],     afr[0], r0, r1);
                mma16816(acc[1][bp * 2],     afr[1], r0, r1);
                mma16816(acc[0][bp * 2 + 1], afr[0], r2, r3);
                mma16816(acc[1][bp * 2 + 1], afr[1], r2, r3);
            }
        }

        if (ch < 63) CP_WAIT0();
        __syncthreads();   // stage s consumed; stage s^1 published
    }

    // --- epilogue: acc -> smem D, per-pixel LN + GELU + store ---
    float* D = (float*)smem;   // reuses p1s/B region (all dead; synced above)
#pragma unroll
    for (int mt = 0; mt < 2; mt++) {
#pragma unroll
        for (int nt = 0; nt < 8; nt++) {
            int row = wp * 32 + mt * 16 + (lid >> 2);
            int col = wo * 64 + nt * 8 + (lid & 3) * 2;
            *(float2*)&D[row * DSTRIDE + col] = make_float2(acc[mt][nt][0], acc[mt][nt][1]);
            *(float2*)&D[(row + 8) * DSTRIDE + col] = make_float2(acc[mt][nt][2], acc[mt][nt][3]);
        }
    }
    __syncthreads();

    {
        const int pix = t >> 2;   // 0..63
        const int q   = t & 3;
        const float* Drow = D + pix * DSTRIDE + q * 64;
        float s1 = 0.0f, s2 = 0.0f;
#pragma unroll
        for (int j = 0; j < 32; j++) {
            float2 v = *(const float2*)&Drow[j * 2];
            s1 += v.x + v.y;
            s2 += v.x * v.x + v.y * v.y;
        }
        // quad reduce
        s1 += __shfl_xor_sync(0xffffffffu, s1, 1);
        s2 += __shfl_xor_sync(0xffffffffu, s2, 1);
        s1 += __shfl_xor_sync(0xffffffffu, s1, 2);
        s2 += __shfl_xor_sync(0xffffffffu, s2, 2);

        float mu = s1 * (1.0f / OUTC);
        float var = s2 * (1.0f / OUTC) - mu * mu;
        float rs = rsqrtf(var + EPS);

        const int P  = pix0 + pix;
        const int bb = P / HW;
        const int hw = P - bb * HW;
        float* obase = out + (size_t)bb * OUTC * HW + hw;
        const float* sg  = (const float*)(smem + OFF_GB);
        const float* sbt = sg + 256;

#pragma unroll
        for (int j = 0; j < 64; j++) {
            int o = q * 64 + j;
            float x = (Drow[j] - mu) * rs * sg[o] + sbt[o];
            float y = 0.5f * x * (1.0f + erff(x * 0.70710678118654752f));
            obase[(size_t)o * HW] = y;
        }
    }
}

// ---------------------------------------------------------------------------
extern "C" void kernel_launch(void* const* d_in, const int* in_sizes, int n_in,
                              void* d_out, int out_size) {
    const float* x1    = (const float*)d_in[0];
    const float* x2    = (const float*)d_in[1];
    const float* W1    = (const float*)d_in[2];
    const float* W2    = (const float*)d_in[3];
    const float* Wp    = (const float*)d_in[4];
    const float* gamma = (const float*)d_in[5];
    const float* beta  = (const float*)d_in[6];
    float* out = (float*)d_out;

    static bool attr_done = false;
    if (!attr_done) {
        cudaFuncSetAttribute(bilinear_mma_kernel,
                             cudaFuncAttributeMaxDynamicSharedMemorySize, SMEM_TOTAL);
        attr_done = true;
    }

    wsplit_kernel<<<(OUTC * KTOT) / 256, 256>>>(Wp);
    proj_kernel<<<dim3(NPIX / 64, 2), 256>>>(x1, x2, W1, W2);
    bilinear_mma_kernel<<<NPIX / 64, 256, SMEM_TOTAL>>>(gamma, beta, out);
}

// round 8
// speedup vs baseline: 6.6285x; 1.1095x over previous
#include <cuda_runtime.h>
#include <cuda_fp16.h>
#include <cstdint>
#include <math.h>

// Problem constants
#define BATCH 8
#define CIN   128
#define HW    3136        // 56*56
#define NPIX  25088       // 8*3136
#define MID   64
#define OUTC  256
#define KTOT  4096        // 64*64
#define EPS   1e-5f

// Scratch (device globals: allocation-free rule)
__device__ __align__(16) float g_p1[(size_t)MID * NPIX];     // [m][pix]
__device__ __align__(16) float g_p2t[(size_t)NPIX * MID];    // [pix][d]  (transposed)
__device__ __align__(16) __half g_Wh[(size_t)OUTC * KTOT];   // fp16 Wp, native [o][k] layout

// ---------------------------------------------------------------------------
// Helpers (arch-portable PTX only: cp.async / ldmatrix / mma.sync)
// ---------------------------------------------------------------------------
__device__ __forceinline__ uint32_t smem_u32(const void* p) {
    uint32_t a;
    asm("{ .reg .u64 t; cvta.to.shared.u64 t, %1; cvt.u32.u64 %0, t; }" : "=r"(a) : "l"(p));
    return a;
}
__device__ __forceinline__ uint32_t h2_u32(__half2 h) {
    union { __half2 h; uint32_t u; } cv;
    cv.h = h;
    return cv.u;
}
__device__ __forceinline__ __half2 u32_h2(uint32_t u) {
    union { __half2 h; uint32_t u; } cv;
    cv.u = u;
    return cv.h;
}
__device__ __forceinline__ void cp16(uint32_t dst, const void* src) {
    asm volatile("cp.async.cg.shared.global [%0], [%1], 16;\n" :: "r"(dst), "l"(src));
}
#define CP_COMMIT() asm volatile("cp.async.commit_group;\n" ::: "memory")
#define CP_WAIT(n)  asm volatile("cp.async.wait_group %0;\n" :: "n"(n) : "memory")

__device__ __forceinline__ void ldsm_x4(uint32_t& r0, uint32_t& r1, uint32_t& r2, uint32_t& r3,
                                        uint32_t addr) {
    asm volatile("ldmatrix.sync.aligned.m8n8.x4.shared.b16 {%0,%1,%2,%3}, [%4];"
                 : "=r"(r0), "=r"(r1), "=r"(r2), "=r"(r3) : "r"(addr));
}
__device__ __forceinline__ void mma16816(float* c, const uint32_t* a, uint32_t b0, uint32_t b1) {
    asm volatile(
        "mma.sync.aligned.m16n8k16.row.col.f32.f16.f16.f32 "
        "{%0,%1,%2,%3}, {%4,%5,%6,%7}, {%8,%9}, {%0,%1,%2,%3};"
        : "+f"(c[0]), "+f"(c[1]), "+f"(c[2]), "+f"(c[3])
        : "r"(a[0]), "r"(a[1]), "r"(a[2]), "r"(a[3]), "r"(b0), "r"(b1));
}

#define SWZ(off) ((off) ^ (((off) >> 3) & 0x70))

// ---------------------------------------------------------------------------
// SMEM layout (per CTA, bytes). CTA tile: 64 pix x 256 o. 2 CTAs/SM.
// 3-stage B pipeline; p1 tile in fp16.
// ---------------------------------------------------------------------------
#define OFF_P1   0          // p1 tile [c][pix] 64x64 fp16 = 8192
#define OFF_B0   8192       // B stages: 256o x 64d fp16 = 32768 each (SW128)
#define OFF_B1   40960
#define OFF_B2   73728
#define OFF_GB   106496     // gamma 256 + beta 256 fp32 = 2048
#define SMEM_TOTAL 108544
// Epilogue D tile reuses [0, 66048): 64 rows x 258 fp32 (padded stride)
#define DSTRIDE  258

// ---------------------------------------------------------------------------
// Fused prologue: projections + Wp->fp16 conversion (one launch).
// blockIdx.y = 0: x1/W1 -> g_p1 [m][pix];  y = 1: x2/W2 -> g_p2t [pix][d].
// Wp conversion strided across ALL blocks.
// ---------------------------------------------------------------------------
__global__ __launch_bounds__(256)
void proj_kernel(const float* __restrict__ x1v, const float* __restrict__ x2v,
                 const float* __restrict__ W1v, const float* __restrict__ W2v,
                 const float* __restrict__ Wp) {
    __shared__ float Ws[CIN][MID];
    const int which = blockIdx.y;
    const float* x  = which ? x2v : x1v;
    const float* Wm = which ? W2v : W1v;

    int t = threadIdx.x;

    // Wp -> fp16, strided over the whole grid (overlaps with projection)
    {
        int gid = (blockIdx.y * gridDim.x + blockIdx.x) * 256 + t;
        int gstride = gridDim.x * 2 * 256;
        for (int idx = gid; idx < OUTC * KTOT; idx += gstride)
            g_Wh[idx] = __float2half_rn(Wp[idx]);
    }

    for (int idx = t; idx < MID * CIN; idx += 256) {
        int c = idx >> 6;
        int m = idx & 63;
        Ws[c][m] = __ldg(&Wm[m * CIN + c]);
    }
    __syncthreads();

    int pixg0 = blockIdx.x * 64;
    int b   = pixg0 / HW;
    int hw0 = pixg0 - b * HW;

    int tx = t & 15;
    int ty = t >> 4;

    const float* xb = x + (size_t)b * CIN * HW + hw0 + tx * 4;

    float acc[4][4];
#pragma unroll
    for (int mi = 0; mi < 4; mi++)
#pragma unroll
        for (int pi = 0; pi < 4; pi++) acc[mi][pi] = 0.0f;

#pragma unroll 4
    for (int c = 0; c < CIN; c++) {
        float4 xv = *(const float4*)(xb + (size_t)c * HW);
        float4 wv = *(const float4*)&Ws[c][ty * 4];
        float xs[4] = {xv.x, xv.y, xv.z, xv.w};
        float wsv[4] = {wv.x, wv.y, wv.z, wv.w};
#pragma unroll
        for (int mi = 0; mi < 4; mi++)
#pragma unroll
            for (int pi = 0; pi < 4; pi++)
                acc[mi][pi] += wsv[mi] * xs[pi];
    }

    if (which == 0) {
#pragma unroll
        for (int mi = 0; mi < 4; mi++) {
            float4 v = make_float4(acc[mi][0], acc[mi][1], acc[mi][2], acc[mi][3]);
            *(float4*)(g_p1 + (size_t)(ty * 4 + mi) * NPIX + pixg0 + tx * 4) = v;
        }
    } else {
        // transposed: g_p2t[pix][d], d = ty*4..+3 contiguous
#pragma unroll
        for (int pi = 0; pi < 4; pi++) {
            float4 v = make_float4(acc[0][pi], acc[1][pi], acc[2][pi], acc[3][pi]);
            *(float4*)(g_p2t + (size_t)(pixg0 + tx * 4 + pi) * MID + ty * 4) = v;
        }
    }
}

// ---------------------------------------------------------------------------
// Main: mma.sync fp16, A fragment built in registers via hmul2 (p2 persistent
// in frag layout, scaled by fp16 p1 scalar). B: 3-stage cp.async pipeline.
// CTA: 64 pix x 256 o, K=4096. 256 threads = 8 warps (2 pix x 4 o groups).
// ---------------------------------------------------------------------------
__global__ __launch_bounds__(256, 2)
void bilinear_mma_kernel(const float* __restrict__ gamma,
                         const float* __restrict__ beta,
                         float* __restrict__ out) {
    extern __shared__ char smem[];
    const uint32_t sbase = smem_u32(smem);

    const int t   = threadIdx.x;
    const int wid = t >> 5;
    const int lid = t & 31;
    const int wp  = wid >> 2;   // pixel group: rows wp*32   (0..1)
    const int wo  = wid & 3;    // o group: cols wo*64       (0..3)
    const int g   = lid >> 2;   // fragment row within 8
    const int q2  = (lid & 3) * 2;
    const int pix0 = blockIdx.x * 64;

    // gamma/beta to smem
    {
        float* gb = (float*)(smem + OFF_GB);
        gb[t]       = __ldg(&gamma[t]);
        gb[256 + t] = __ldg(&beta[t]);
    }

    // p1 tile -> smem as fp16  [c][64 pix]
    __half* p1s = (__half*)(smem + OFF_P1);
#pragma unroll
    for (int r = 0; r < 16; r++) {
        int i = t + r * 256;
        int c = i >> 6, px = i & 63;
        p1s[i] = __float2half_rn(g_p1[(size_t)c * NPIX + pix0 + px]);
    }

    // p2 persistent fragment regs (packed half2): p2f[((mt*2+h)*4+kk)*2+j]
    //   row r = wp*32 + mt*16 + h*8 + g ; k = kk*16 + q2 + j*8 ; half2 (k, k+1)
    uint32_t p2f[32];
#pragma unroll
    for (int mt = 0; mt < 2; mt++)
#pragma unroll
        for (int h = 0; h < 2; h++) {
            const float* prow = g_p2t + (size_t)(pix0 + wp * 32 + mt * 16 + h * 8 + g) * MID;
#pragma unroll
            for (int kk = 0; kk < 4; kk++)
#pragma unroll
                for (int j = 0; j < 2; j++) {
                    float2 v = *(const float2*)&prow[kk * 16 + q2 + j * 8];
                    p2f[((mt * 2 + h) * 4 + kk) * 2 + j] =
                        h2_u32(__floats2half2_rn(v.x, v.y));
                }
        }

    const uint32_t offB[3] = {OFF_B0, OFF_B1, OFF_B2};

    auto fetch_B = [&](int ch, int st) {
        const __half* bh = g_Wh + (size_t)ch * 64;
#pragma unroll
        for (int r = 0; r < 8; r++) {
            int idx = t + r * 256;       // 0..2047
            int o   = idx >> 3;
            int seg = idx & 7;
            uint32_t doff = SWZ((uint32_t)(o * 128 + seg * 16));
            cp16(sbase + offB[st] + doff, bh + (size_t)o * KTOT + seg * 8);
        }
        CP_COMMIT();
    };

    float acc[2][8][4];
#pragma unroll
    for (int mt = 0; mt < 2; mt++)
#pragma unroll
        for (int nt = 0; nt < 8; nt++)
#pragma unroll
            for (int i = 0; i < 4; i++) acc[mt][nt][i] = 0.0f;

    // Prologue: stages 0 and 1 in flight; stage 0 must be complete.
    fetch_B(0, 0);
    fetch_B(1, 1);
    CP_WAIT(1);
    __syncthreads();            // stage 0 + p1s published

    const int b_row_l = ((lid >> 4) << 3) + (lid & 7);
    const int b_hi16  = ((lid >> 3) & 1) * 16;

    int snum = 0;   // stage index = ch % 3, tracked incrementally
    for (int ch = 0; ch < 64; ch++) {
        const int s = snum;
        snum = (snum == 2) ? 0 : snum + 1;

        if (ch < 62) {
            int st2 = (ch + 2) % 3;
            fetch_B(ch + 2, st2);
        }

        // p1 scalars for this chunk (fp16, broadcast LDS within quads)
        uint32_t p1h2[2][2];
#pragma unroll
        for (int mt = 0; mt < 2; mt++)
#pragma unroll
            for (int h = 0; h < 2; h++)
                p1h2[mt][h] = h2_u32(__half2half2(
                    p1s[ch * 64 + wp * 32 + mt * 16 + h * 8 + g]));

        const uint32_t bb = sbase + offB[s];
#pragma unroll
        for (int kk = 0; kk < 4; kk++) {
            // A fragments in registers: afr[mt] = {h0j0, h1j0, h0j1, h1j1}
            uint32_t afr[2][4];
#pragma unroll
            for (int mt = 0; mt < 2; mt++)
#pragma unroll
                for (int rr = 0; rr < 4; rr++) {
                    int h = rr & 1, j = rr >> 1;
                    afr[mt][rr] = h2_u32(__hmul2(
                        u32_h2(p1h2[mt][h]),
                        u32_h2(p2f[((mt * 2 + h) * 4 + kk) * 2 + j])));
                }

            // B: load per bp and consume immediately (cap register liveness)
#pragma unroll
            for (int bp = 0; bp < 4; bp++) {
                int orow = wo * 64 + bp * 16 + b_row_l;
                uint32_t addr = bb + SWZ((uint32_t)(orow * 128 + kk * 32 + b_hi16));
                uint32_t r0, r1, r2, r3;
                ldsm_x4(r0, r1, r2, r3, addr);
                mma16816(acc[0][bp * 2],     afr[0], r0, r1);
                mma16816(acc[1][bp * 2],     afr[1], r0, r1);
                mma16816(acc[0][bp * 2 + 1], afr[0], r2, r3);
                mma16816(acc[1][bp * 2 + 1], afr[1], r2, r3);
            }
        }

        // ensure next chunk's stage is complete before the barrier
        if (ch < 62) { CP_WAIT(1); } else { CP_WAIT(0); }
        __syncthreads();   // stage s consumed; safe to overwrite next iter
    }

    // --- epilogue: acc -> smem D, per-pixel LN + GELU + store ---
    float* D = (float*)smem;   // reuses p1s/B region (all dead; synced above)
#pragma unroll
    for (int mt = 0; mt < 2; mt++) {
#pragma unroll
        for (int nt = 0; nt < 8; nt++) {
            int row = wp * 32 + mt * 16 + (lid >> 2);
            int col = wo * 64 + nt * 8 + (lid & 3) * 2;
            *(float2*)&D[row * DSTRIDE + col] = make_float2(acc[mt][nt][0], acc[mt][nt][1]);
            *(float2*)&D[(row + 8) * DSTRIDE + col] = make_float2(acc[mt][nt][2], acc[mt][nt][3]);
        }
    }
    __syncthreads();

    {
        const int pix = t >> 2;   // 0..63
        const int q   = t & 3;
        const float* Drow = D + pix * DSTRIDE + q * 64;
        float s1 = 0.0f, s2 = 0.0f;
#pragma unroll
        for (int j = 0; j < 32; j++) {
            float2 v = *(const float2*)&Drow[j * 2];
            s1 += v.x + v.y;
            s2 += v.x * v.x + v.y * v.y;
        }
        // quad reduce
        s1 += __shfl_xor_sync(0xffffffffu, s1, 1);
        s2 += __shfl_xor_sync(0xffffffffu, s2, 1);
        s1 += __shfl_xor_sync(0xffffffffu, s1, 2);
        s2 += __shfl_xor_sync(0xffffffffu, s2, 2);

        float mu = s1 * (1.0f / OUTC);
        float var = s2 * (1.0f / OUTC) - mu * mu;
        float rs = rsqrtf(var + EPS);

        const int P  = pix0 + pix;
        const int bb = P / HW;
        const int hw = P - bb * HW;
        float* obase = out + (size_t)bb * OUTC * HW + hw;
        const float* sg  = (const float*)(smem + OFF_GB);
        const float* sbt = sg + 256;

#pragma unroll
        for (int j = 0; j < 64; j++) {
            int o = q * 64 + j;
            float x = (Drow[j] - mu) * rs * sg[o] + sbt[o];
            float y = 0.5f * x * (1.0f + erff(x * 0.70710678118654752f));
            obase[(size_t)o * HW] = y;
        }
    }
}

// ---------------------------------------------------------------------------
extern "C" void kernel_launch(void* const* d_in, const int* in_sizes, int n_in,
                              void* d_out, int out_size) {
    const float* x1    = (const float*)d_in[0];
    const float* x2    = (const float*)d_in[1];
    const float* W1    = (const float*)d_in[2];
    const float* W2    = (const float*)d_in[3];
    const float* Wp    = (const float*)d_in[4];
    const float* gamma = (const float*)d_in[5];
    const float* beta  = (const float*)d_in[6];
    float* out = (float*)d_out;

    static bool attr_done = false;
    if (!attr_done) {
        cudaFuncSetAttribute(bilinear_mma_kernel,
                             cudaFuncAttributeMaxDynamicSharedMemorySize, SMEM_TOTAL);
        attr_done = true;
    }

    proj_kernel<<<dim3(NPIX / 64, 2), 256>>>(x1, x2, W1, W2, Wp);
    bilinear_mma_kernel<<<NPIX / 64, 256, SMEM_TOTAL>>>(gamma, beta, out);
}

// round 9
// speedup vs baseline: 7.0461x; 1.0630x over previous
#include <cuda_runtime.h>
#include <cuda_fp16.h>
#include <cstdint>
#include <math.h>

// Problem constants
#define BATCH 8
#define CIN   128
#define HW    3136        // 56*56
#define NPIX  25088       // 8*3136
#define MID   64
#define OUTC  256
#define KTOT  4096        // 64*64
#define EPS   1e-5f

// Scratch (device globals: allocation-free rule)
__device__ __align__(16) __half g_Wh[(size_t)OUTC * KTOT];   // fp16 Wp, native [o][k] layout

// ---------------------------------------------------------------------------
// Helpers (arch-portable PTX only: cp.async / ldmatrix / mma.sync)
// ---------------------------------------------------------------------------
__device__ __forceinline__ uint32_t smem_u32(const void* p) {
    uint32_t a;
    asm("{ .reg .u64 t; cvta.to.shared.u64 t, %1; cvt.u32.u64 %0, t; }" : "=r"(a) : "l"(p));
    return a;
}
__device__ __forceinline__ uint32_t h2_u32(__half2 h) {
    union { __half2 h; uint32_t u; } cv;
    cv.h = h;
    return cv.u;
}
__device__ __forceinline__ __half2 u32_h2(uint32_t u) {
    union { __half2 h; uint32_t u; } cv;
    cv.u = u;
    return cv.h;
}
__device__ __forceinline__ void cp16(uint32_t dst, const void* src) {
    asm volatile("cp.async.cg.shared.global [%0], [%1], 16;\n" :: "r"(dst), "l"(src));
}
#define CP_COMMIT() asm volatile("cp.async.commit_group;\n" ::: "memory")
#define CP_WAIT(n)  asm volatile("cp.async.wait_group %0;\n" :: "n"(n) : "memory")

__device__ __forceinline__ void ldsm_x4(uint32_t& r0, uint32_t& r1, uint32_t& r2, uint32_t& r3,
                                        uint32_t addr) {
    asm volatile("ldmatrix.sync.aligned.m8n8.x4.shared.b16 {%0,%1,%2,%3}, [%4];"
                 : "=r"(r0), "=r"(r1), "=r"(r2), "=r"(r3) : "r"(addr));
}
__device__ __forceinline__ void mma16816(float* c, const uint32_t* a, uint32_t b0, uint32_t b1) {
    asm volatile(
        "mma.sync.aligned.m16n8k16.row.col.f32.f16.f16.f32 "
        "{%0,%1,%2,%3}, {%4,%5,%6,%7}, {%8,%9}, {%0,%1,%2,%3};"
        : "+f"(c[0]), "+f"(c[1]), "+f"(c[2]), "+f"(c[3])
        : "r"(a[0]), "r"(a[1]), "r"(a[2]), "r"(a[3]), "r"(b0), "r"(b1));
}

#define SWZ(off) ((off) ^ (((off) >> 3) & 0x70))

// ---------------------------------------------------------------------------
// SMEM layout (per CTA, bytes). CTA tile: 64 pix x 256 o. 2 CTAs/SM.
// 3-stage B pipeline; p1 tile fp16. Prologue temps overlay the B stages:
//   Ws1 -> OFF_B0 (32KB), Ws2 -> OFF_B1 (32KB), p2s tmp -> OFF_B2 (17.4KB)
// ---------------------------------------------------------------------------
#define OFF_P1   0          // p1 tile [m][pix] 64x64 fp16 = 8192
#define OFF_B0   8192       // B stages: 256o x 64d fp16 = 32768 each (SW128)
#define OFF_B1   40960
#define OFF_B2   73728
#define OFF_GB   106496     // gamma 256 + beta 256 fp32 = 2048
#define SMEM_TOTAL 108544
#define P2S_STRIDE 68       // p2s tmp [pix][d] fp32, padded row stride
// Epilogue D tile reuses [0, 66048): 64 rows x 258 fp32 (padded stride)
#define DSTRIDE  258

// ---------------------------------------------------------------------------
// Wp -> fp16 (native [o][k] layout preserved). Tiny DRAM-bound kernel; must
// complete before the main kernel reads g_Wh.
// ---------------------------------------------------------------------------
__global__ void wsplit_kernel(const float* __restrict__ Wp) {
    int idx = blockIdx.x * 256 + threadIdx.x;
    g_Wh[idx] = __float2half_rn(Wp[idx]);
}

// ---------------------------------------------------------------------------
// Fused: in-CTA projections + mma.sync fp16 GEMM + LN + exact GELU.
// CTA: 64 pix x 256 o, K=4096. 256 threads = 8 warps (2 pix x 4 o groups).
// A fragment built in registers (p2 persistent in frag layout, scaled per
// chunk by fp16 p1 scalar via hmul2). B: 3-stage cp.async pipeline.
// ---------------------------------------------------------------------------
__global__ __launch_bounds__(256, 2)
void bilinear_mma_kernel(const float* __restrict__ x1,
                         const float* __restrict__ x2,
                         const float* __restrict__ W1,
                         const float* __restrict__ W2,
                         const float* __restrict__ gamma,
                         const float* __restrict__ beta,
                         float* __restrict__ out) {
    extern __shared__ char smem[];
    const uint32_t sbase = smem_u32(smem);

    const int t   = threadIdx.x;
    const int wid = t >> 5;
    const int lid = t & 31;
    const int wp  = wid >> 2;   // pixel group: rows wp*32   (0..1)
    const int wo  = wid & 3;    // o group: cols wo*64       (0..3)
    const int g   = lid >> 2;   // fragment row within 8
    const int q2  = (lid & 3) * 2;
    const int pix0 = blockIdx.x * 64;
    const int b   = pix0 / HW;
    const int hw0 = pix0 - b * HW;

    // gamma/beta to smem
    {
        float* gb = (float*)(smem + OFF_GB);
        gb[t]       = __ldg(&gamma[t]);
        gb[256 + t] = __ldg(&beta[t]);
    }

    // ===================== in-CTA projection phase =====================
    // Ws1/Ws2 transposed [c][m] into B0/B1 regions (W is L2-resident)
    float* Ws1 = (float*)(smem + OFF_B0);
    float* Ws2 = (float*)(smem + OFF_B1);
    for (int idx = t; idx < MID * CIN; idx += 256) {
        int c = idx >> 6;
        int m = idx & 63;
        Ws1[idx] = __ldg(&W1[m * CIN + c]);
        Ws2[idx] = __ldg(&W2[m * CIN + c]);
    }
    __syncthreads();

    const int tx = t & 15;    // pixel quad: pixels tx*4..+3
    const int ty = t >> 4;    // m quad:     m = ty*4..+3

    __half* p1s = (__half*)(smem + OFF_P1);       // [m][pix] fp16
    float*  p2s = (float*)(smem + OFF_B2);        // [pix][d] fp32, stride 68

    {
        const float* xb1 = x1 + (size_t)b * CIN * HW + hw0 + tx * 4;
        const float* xb2 = x2 + (size_t)b * CIN * HW + hw0 + tx * 4;

        float a1[4][4], a2[4][4];
#pragma unroll
        for (int mi = 0; mi < 4; mi++)
#pragma unroll
            for (int pi = 0; pi < 4; pi++) { a1[mi][pi] = 0.0f; a2[mi][pi] = 0.0f; }

#pragma unroll 4
        for (int c = 0; c < CIN; c++) {
            float4 xv1 = *(const float4*)(xb1 + (size_t)c * HW);
            float4 xv2 = *(const float4*)(xb2 + (size_t)c * HW);
            float4 wv1 = *(const float4*)&Ws1[c * 64 + ty * 4];
            float4 wv2 = *(const float4*)&Ws2[c * 64 + ty * 4];
            float xs1[4] = {xv1.x, xv1.y, xv1.z, xv1.w};
            float xs2[4] = {xv2.x, xv2.y, xv2.z, xv2.w};
            float w1v[4] = {wv1.x, wv1.y, wv1.z, wv1.w};
            float w2v[4] = {wv2.x, wv2.y, wv2.z, wv2.w};
#pragma unroll
            for (int mi = 0; mi < 4; mi++)
#pragma unroll
                for (int pi = 0; pi < 4; pi++) {
                    a1[mi][pi] += w1v[mi] * xs1[pi];
                    a2[mi][pi] += w2v[mi] * xs2[pi];
                }
        }
        __syncthreads();   // Ws reads done; B0/B1 still hold Ws until refetch

        // p1 -> p1s fp16 [m][pix]
#pragma unroll
        for (int mi = 0; mi < 4; mi++)
#pragma unroll
            for (int pi = 0; pi < 4; pi++)
                p1s[(ty * 4 + mi) * 64 + tx * 4 + pi] = __float2half_rn(a1[mi][pi]);

        // p2 -> p2s fp32 [pix][d] (temp in B2 region)
#pragma unroll
        for (int pi = 0; pi < 4; pi++)
#pragma unroll
            for (int mi = 0; mi < 4; mi++)
                p2s[(tx * 4 + pi) * P2S_STRIDE + ty * 4 + mi] = a2[mi][pi];
    }
    __syncthreads();   // p1s + p2s published

    // p2 persistent fragment regs (packed half2): p2f[((mt*2+h)*4+kk)*2+j]
    //   row r = wp*32 + mt*16 + h*8 + g ; k = kk*16 + q2 + j*8 ; half2 (k, k+1)
    uint32_t p2f[32];
#pragma unroll
    for (int mt = 0; mt < 2; mt++)
#pragma unroll
        for (int h = 0; h < 2; h++) {
            const float* prow = p2s + (wp * 32 + mt * 16 + h * 8 + g) * P2S_STRIDE;
#pragma unroll
            for (int kk = 0; kk < 4; kk++)
#pragma unroll
                for (int j = 0; j < 2; j++) {
                    float2 v = *(const float2*)&prow[kk * 16 + q2 + j * 8];
                    p2f[((mt * 2 + h) * 4 + kk) * 2 + j] =
                        h2_u32(__floats2half2_rn(v.x, v.y));
                }
        }
    __syncthreads();   // p2s reads complete; B regions free for the pipeline

    // ===================== mainloop =====================
    const uint32_t offB[3] = {OFF_B0, OFF_B1, OFF_B2};

    auto fetch_B = [&](int ch, int st) {
        const __half* bh = g_Wh + (size_t)ch * 64;
#pragma unroll
        for (int r = 0; r < 8; r++) {
            int idx = t + r * 256;       // 0..2047
            int o   = idx >> 3;
            int seg = idx & 7;
            uint32_t doff = SWZ((uint32_t)(o * 128 + seg * 16));
            cp16(sbase + offB[st] + doff, bh + (size_t)o * KTOT + seg * 8);
        }
        CP_COMMIT();
    };

    float acc[2][8][4];
#pragma unroll
    for (int mt = 0; mt < 2; mt++)
#pragma unroll
        for (int nt = 0; nt < 8; nt++)
#pragma unroll
            for (int i = 0; i < 4; i++) acc[mt][nt][i] = 0.0f;

    // Prologue: stages 0 and 1 in flight; stage 0 must be complete.
    fetch_B(0, 0);
    fetch_B(1, 1);
    CP_WAIT(1);
    __syncthreads();            // stage 0 published

    const int b_row_l = ((lid >> 4) << 3) + (lid & 7);
    const int b_hi16  = ((lid >> 3) & 1) * 16;

    int snum = 0;   // stage index = ch % 3, tracked incrementally
    for (int ch = 0; ch < 64; ch++) {
        const int s = snum;
        snum = (snum == 2) ? 0 : snum + 1;

        if (ch < 62) {
            int st2 = (ch + 2) % 3;
            fetch_B(ch + 2, st2);
        }

        // p1 scalars for this chunk (fp16, broadcast LDS within quads)
        uint32_t p1h2[2][2];
#pragma unroll
        for (int mt = 0; mt < 2; mt++)
#pragma unroll
            for (int h = 0; h < 2; h++)
                p1h2[mt][h] = h2_u32(__half2half2(
                    p1s[ch * 64 + wp * 32 + mt * 16 + h * 8 + g]));

        const uint32_t bb = sbase + offB[s];
#pragma unroll
        for (int kk = 0; kk < 4; kk++) {
            // A fragments in registers: afr[mt] = {h0j0, h1j0, h0j1, h1j1}
            uint32_t afr[2][4];
#pragma unroll
            for (int mt = 0; mt < 2; mt++)
#pragma unroll
                for (int rr = 0; rr < 4; rr++) {
                    int h = rr & 1, j = rr >> 1;
                    afr[mt][rr] = h2_u32(__hmul2(
                        u32_h2(p1h2[mt][h]),
                        u32_h2(p2f[((mt * 2 + h) * 4 + kk) * 2 + j])));
                }

            // B: load per bp and consume immediately (cap register liveness)
#pragma unroll
            for (int bp = 0; bp < 4; bp++) {
                int orow = wo * 64 + bp * 16 + b_row_l;
                uint32_t addr = bb + SWZ((uint32_t)(orow * 128 + kk * 32 + b_hi16));
                uint32_t r0, r1, r2, r3;
                ldsm_x4(r0, r1, r2, r3, addr);
                mma16816(acc[0][bp * 2],     afr[0], r0, r1);
                mma16816(acc[1][bp * 2],     afr[1], r0, r1);
                mma16816(acc[0][bp * 2 + 1], afr[0], r2, r3);
                mma16816(acc[1][bp * 2 + 1], afr[1], r2, r3);
            }
        }

        // ensure next chunk's stage is complete before the barrier
        if (ch < 62) { CP_WAIT(1); } else { CP_WAIT(0); }
        __syncthreads();   // stage s consumed; safe to overwrite next iter
    }

    // --- epilogue: acc -> smem D, per-pixel LN + GELU + store ---
    float* D = (float*)smem;   // reuses p1s/B region (all dead; synced above)
#pragma unroll
    for (int mt = 0; mt < 2; mt++) {
#pragma unroll
        for (int nt = 0; nt < 8; nt++) {
            int row = wp * 32 + mt * 16 + (lid >> 2);
            int col = wo * 64 + nt * 8 + (lid & 3) * 2;
            *(float2*)&D[row * DSTRIDE + col] = make_float2(acc[mt][nt][0], acc[mt][nt][1]);
            *(float2*)&D[(row + 8) * DSTRIDE + col] = make_float2(acc[mt][nt][2], acc[mt][nt][3]);
        }
    }
    __syncthreads();

    {
        const int pix = t >> 2;   // 0..63
        const int q   = t & 3;
        const float* Drow = D + pix * DSTRIDE + q * 64;
        float s1 = 0.0f, s2 = 0.0f;
#pragma unroll
        for (int j = 0; j < 32; j++) {
            float2 v = *(const float2*)&Drow[j * 2];
            s1 += v.x + v.y;
            s2 += v.x * v.x + v.y * v.y;
        }
        // quad reduce
        s1 += __shfl_xor_sync(0xffffffffu, s1, 1);
        s2 += __shfl_xor_sync(0xffffffffu, s2, 1);
        s1 += __shfl_xor_sync(0xffffffffu, s1, 2);
        s2 += __shfl_xor_sync(0xffffffffu, s2, 2);

        float mu = s1 * (1.0f / OUTC);
        float var = s2 * (1.0f / OUTC) - mu * mu;
        float rs = rsqrtf(var + EPS);

        const int P  = pix0 + pix;
        const int bb2 = P / HW;
        const int hw = P - bb2 * HW;
        float* obase = out + (size_t)bb2 * OUTC * HW + hw;
        const float* sg  = (const float*)(smem + OFF_GB);
        const float* sbt = sg + 256;

#pragma unroll
        for (int j = 0; j < 64; j++) {
            int o = q * 64 + j;
            float x = (Drow[j] - mu) * rs * sg[o] + sbt[o];
            float y = 0.5f * x * (1.0f + erff(x * 0.70710678118654752f));
            obase[(size_t)o * HW] = y;
        }
    }
}

// ---------------------------------------------------------------------------
extern "C" void kernel_launch(void* const* d_in, const int* in_sizes, int n_in,
                              void* d_out, int out_size) {
    const float* x1    = (const float*)d_in[0];
    const float* x2    = (const float*)d_in[1];
    const float* W1    = (const float*)d_in[2];
    const float* W2    = (const float*)d_in[3];
    const float* Wp    = (const float*)d_in[4];
    const float* gamma = (const float*)d_in[5];
    const float* beta  = (const float*)d_in[6];
    float* out = (float*)d_out;

    static bool attr_done = false;
    if (!attr_done) {
        cudaFuncSetAttribute(bilinear_mma_kernel,
                             cudaFuncAttributeMaxDynamicSharedMemorySize, SMEM_TOTAL);
        attr_done = true;
    }

    wsplit_kernel<<<(OUTC * KTOT) / 256, 256>>>(Wp);
    bilinear_mma_kernel<<<NPIX / 64, 256, SMEM_TOTAL>>>(x1, x2, W1, W2, gamma, beta, out);
}